// round 2
// baseline (speedup 1.0000x reference)
#include <cuda_runtime.h>
#include <math.h>

#define TOK 4096
#define DM 1024
#define QPJ 512
#define SEQ 2048
#define NH 16
#define DH 64

// -------- scratch (static device globals: allocation-free) --------
__device__ float g_xq [TOK * DM];
__device__ float g_xkv[TOK * DM];
__device__ float g_t1 [TOK * QPJ];
__device__ float g_cq [TOK * QPJ];
__device__ float g_Q  [TOK * DM];
__device__ float g_t2 [TOK * DM];
__device__ float g_ckv[TOK * DM];
__device__ float g_KV [TOK * 2 * DM];
__device__ float g_ao [TOK * DM];

// ------------------------- LayerNorm -------------------------
__global__ __launch_bounds__(256) void ln_kernel(
    const float* __restrict__ in, const float* __restrict__ gg,
    const float* __restrict__ bb, float* __restrict__ out, int D)
{
    int row = blockIdx.x;
    const float* x = in + (size_t)row * D;
    float* o = out + (size_t)row * D;

    float s = 0.f, s2 = 0.f;
    for (int i = threadIdx.x; i < D; i += 256) {
        float v = x[i];
        s += v; s2 += v * v;
    }
    __shared__ float red[64];
    #pragma unroll
    for (int m = 16; m; m >>= 1) {
        s  += __shfl_xor_sync(0xffffffffu, s,  m);
        s2 += __shfl_xor_sync(0xffffffffu, s2, m);
    }
    int wid = threadIdx.x >> 5, lid = threadIdx.x & 31;
    if (lid == 0) { red[wid] = s; red[32 + wid] = s2; }
    __syncthreads();
    if (wid == 0) {
        s  = (lid < 8) ? red[lid]      : 0.f;
        s2 = (lid < 8) ? red[32 + lid] : 0.f;
        #pragma unroll
        for (int m = 4; m; m >>= 1) {
            s  += __shfl_xor_sync(0xffffffffu, s,  m);
            s2 += __shfl_xor_sync(0xffffffffu, s2, m);
        }
        if (lid == 0) { red[0] = s; red[1] = s2; }
    }
    __syncthreads();
    float mu  = red[0] / (float)D;
    float var = red[1] / (float)D - mu * mu;
    float r   = rsqrtf(var + 1e-5f);
    for (int i = threadIdx.x; i < D; i += 256)
        o[i] = (x[i] - mu) * r * gg[i] + bb[i];
}

// ------------------------- SGEMM (128x128x8, 8x8/thread) -------------------------
// C[M,N] = scale * A[M,K] @ B   (TRANSB=0: B[K,N];  TRANSB=1: B[N,K], i.e. A@B^T)
// All dims multiples of 128/8 for this problem -> no bounds checks.
template<bool TRANSB>
__global__ __launch_bounds__(256) void sgemm_kernel(
    const float* __restrict__ A, const float* __restrict__ B,
    float* __restrict__ C, int M, int N, int K, float scale)
{
    __shared__ float As[8][132];
    __shared__ float Bs[8][132];

    int tid = threadIdx.x;
    int tx = tid & 15, ty = tid >> 4;
    int row0 = blockIdx.y * 128;
    int col0 = blockIdx.x * 128;

    float acc[8][8];
    #pragma unroll
    for (int i = 0; i < 8; i++)
        #pragma unroll
        for (int j = 0; j < 8; j++) acc[i][j] = 0.f;

    int a_r  = tid >> 1;
    int a_c4 = (tid & 1) * 4;
    int b_r, b_c4;
    if (TRANSB) { b_r = tid >> 1; b_c4 = (tid & 1) * 4; }
    else        { b_r = tid >> 5; b_c4 = (tid & 31) * 4; }

    for (int kt = 0; kt < K; kt += 8) {
        float4 av = *(const float4*)&A[(size_t)(row0 + a_r) * K + kt + a_c4];
        As[a_c4 + 0][a_r] = av.x;
        As[a_c4 + 1][a_r] = av.y;
        As[a_c4 + 2][a_r] = av.z;
        As[a_c4 + 3][a_r] = av.w;
        if (TRANSB) {
            float4 bv = *(const float4*)&B[(size_t)(col0 + b_r) * K + kt + b_c4];
            Bs[b_c4 + 0][b_r] = bv.x;
            Bs[b_c4 + 1][b_r] = bv.y;
            Bs[b_c4 + 2][b_r] = bv.z;
            Bs[b_c4 + 3][b_r] = bv.w;
        } else {
            float4 bv = *(const float4*)&B[(size_t)(kt + b_r) * N + col0 + b_c4];
            *(float4*)&Bs[b_r][b_c4] = bv;
        }
        __syncthreads();

        #pragma unroll
        for (int k = 0; k < 8; ++k) {
            float4 a0 = *(const float4*)&As[k][ty * 8];
            float4 a1 = *(const float4*)&As[k][ty * 8 + 4];
            float4 b0 = *(const float4*)&Bs[k][tx * 8];
            float4 b1 = *(const float4*)&Bs[k][tx * 8 + 4];
            float ar[8] = {a0.x, a0.y, a0.z, a0.w, a1.x, a1.y, a1.z, a1.w};
            float br[8] = {b0.x, b0.y, b0.z, b0.w, b1.x, b1.y, b1.z, b1.w};
            #pragma unroll
            for (int i = 0; i < 8; i++)
                #pragma unroll
                for (int j = 0; j < 8; j++)
                    acc[i][j] = fmaf(ar[i], br[j], acc[i][j]);
        }
        __syncthreads();
    }

    #pragma unroll
    for (int i = 0; i < 8; i++) {
        float4 v0 = make_float4(acc[i][0] * scale, acc[i][1] * scale,
                                acc[i][2] * scale, acc[i][3] * scale);
        float4 v1 = make_float4(acc[i][4] * scale, acc[i][5] * scale,
                                acc[i][6] * scale, acc[i][7] * scale);
        size_t off = (size_t)(row0 + ty * 8 + i) * N + col0 + tx * 8;
        *(float4*)&C[off]     = v0;
        *(float4*)&C[off + 4] = v1;
    }
}

// ------------------------- Causal Flash Attention -------------------------
// grid: (SEQ/64, NH, B).  64 q-rows per block, 256 threads as 16x16,
// each thread owns a 4x4 microtile (rows ty*4.., out-dims/score-cols tx*4..).
// Q already scaled by 1/sqrt(dh).
__global__ __launch_bounds__(256) void attn_kernel(
    const float* __restrict__ Q, const float* __restrict__ KV,
    float* __restrict__ O)
{
    extern __shared__ float sm[];
    float* Qt = sm;                  // [64][68]  Qt[d][r]
    float* Kt = sm + 64 * 68;        // [64][68]  Kt[d][c]
    float* Vs = sm + 2 * 64 * 68;    // [64][68]  Vs[k][d]
    float* Pt = sm + 3 * 64 * 68;    // [64][68]  Pt[k][r]

    int tid = threadIdx.x;
    int tx = tid & 15, ty = tid >> 4;
    int q0 = blockIdx.x * 64;
    int h  = blockIdx.y;
    int bb = blockIdx.z;

    // load Q tile (transposed)
    #pragma unroll
    for (int rep = 0; rep < 4; rep++) {
        int idx = tid + rep * 256;
        int r  = idx >> 4;
        int d4 = (idx & 15) * 4;
        float4 v = *(const float4*)&Q[(size_t)(bb * SEQ + q0 + r) * DM + h * DH + d4];
        Qt[(d4 + 0) * 68 + r] = v.x;
        Qt[(d4 + 1) * 68 + r] = v.y;
        Qt[(d4 + 2) * 68 + r] = v.z;
        Qt[(d4 + 3) * 68 + r] = v.w;
    }

    float m_i[4], l_i[4], acc[4][4];
    #pragma unroll
    for (int i = 0; i < 4; i++) {
        m_i[i] = -INFINITY; l_i[i] = 0.f;
        #pragma unroll
        for (int j = 0; j < 4; j++) acc[i][j] = 0.f;
    }

    int ktiles = blockIdx.x + 1;
    for (int kt = 0; kt < ktiles; kt++) {
        int t0 = kt * 64;
        __syncthreads();   // previous iteration's PV reads done
        #pragma unroll
        for (int rep = 0; rep < 4; rep++) {
            int idx = tid + rep * 256;
            int c  = idx >> 4;
            int d4 = (idx & 15) * 4;
            size_t tok = (size_t)(bb * SEQ + t0 + c);
            float4 k4 = *(const float4*)&KV[tok * 2048 + h * DH + d4];
            Kt[(d4 + 0) * 68 + c] = k4.x;
            Kt[(d4 + 1) * 68 + c] = k4.y;
            Kt[(d4 + 2) * 68 + c] = k4.z;
            Kt[(d4 + 3) * 68 + c] = k4.w;
            float4 v4 = *(const float4*)&KV[tok * 2048 + 1024 + h * DH + d4];
            *(float4*)&Vs[c * 68 + d4] = v4;
        }
        __syncthreads();

        // scores: S = Q @ K^T  (4x4 per thread)
        float s[4][4];
        #pragma unroll
        for (int i = 0; i < 4; i++)
            #pragma unroll
            for (int j = 0; j < 4; j++) s[i][j] = 0.f;

        #pragma unroll 8
        for (int d = 0; d < 64; d++) {
            float4 q4 = *(const float4*)&Qt[d * 68 + ty * 4];
            float4 k4 = *(const float4*)&Kt[d * 68 + tx * 4];
            float qr[4] = {q4.x, q4.y, q4.z, q4.w};
            float kr[4] = {k4.x, k4.y, k4.z, k4.w};
            #pragma unroll
            for (int i = 0; i < 4; i++)
                #pragma unroll
                for (int j = 0; j < 4; j++)
                    s[i][j] = fmaf(qr[i], kr[j], s[i][j]);
        }

        // causal mask (only diagonal tile)
        if (kt == ktiles - 1) {
            #pragma unroll
            for (int i = 0; i < 4; i++)
                #pragma unroll
                for (int j = 0; j < 4; j++)
                    if (t0 + tx * 4 + j > q0 + ty * 4 + i) s[i][j] = -INFINITY;
        }

        // online softmax per row + write P^T
        #pragma unroll
        for (int i = 0; i < 4; i++) {
            float tm = fmaxf(fmaxf(s[i][0], s[i][1]), fmaxf(s[i][2], s[i][3]));
            #pragma unroll
            for (int m = 1; m < 16; m <<= 1)
                tm = fmaxf(tm, __shfl_xor_sync(0xffffffffu, tm, m));
            float mn = fmaxf(m_i[i], tm);
            float sc = __expf(m_i[i] - mn);   // -inf -> 0 on first tile
            m_i[i] = mn;
            float p[4], ps = 0.f;
            #pragma unroll
            for (int j = 0; j < 4; j++) { p[j] = __expf(s[i][j] - mn); ps += p[j]; }
            #pragma unroll
            for (int m = 1; m < 16; m <<= 1)
                ps += __shfl_xor_sync(0xffffffffu, ps, m);
            l_i[i] = l_i[i] * sc + ps;
            #pragma unroll
            for (int j = 0; j < 4; j++) {
                acc[i][j] *= sc;
                Pt[(tx * 4 + j) * 68 + ty * 4 + i] = p[j];
            }
        }
        __syncthreads();

        // O += P @ V
        #pragma unroll 8
        for (int k = 0; k < 64; k++) {
            float4 p4 = *(const float4*)&Pt[k * 68 + ty * 4];
            float4 v4 = *(const float4*)&Vs[k * 68 + tx * 4];
            float pr[4] = {p4.x, p4.y, p4.z, p4.w};
            float vr[4] = {v4.x, v4.y, v4.z, v4.w};
            #pragma unroll
            for (int i = 0; i < 4; i++)
                #pragma unroll
                for (int j = 0; j < 4; j++)
                    acc[i][j] = fmaf(pr[i], vr[j], acc[i][j]);
        }
    }

    // epilogue
    #pragma unroll
    for (int i = 0; i < 4; i++) {
        float inv = 1.f / l_i[i];
        size_t off = (size_t)(bb * SEQ + q0 + ty * 4 + i) * DM + h * DH + tx * 4;
        float4 v = make_float4(acc[i][0] * inv, acc[i][1] * inv,
                               acc[i][2] * inv, acc[i][3] * inv);
        *(float4*)&O[off] = v;
    }
}

// ------------------------- launch -------------------------
extern "C" void kernel_launch(void* const* d_in, const int* in_sizes, int n_in,
                              void* d_out, int out_size)
{
    (void)in_sizes; (void)n_in; (void)out_size;
    const float* x       = (const float*)d_in[0];
    const float* W_dq    = (const float*)d_in[1];
    const float* W_uq    = (const float*)d_in[2];
    const float* q_ln_g  = (const float*)d_in[3];
    const float* q_ln_b  = (const float*)d_in[4];
    const float* W_dkv   = (const float*)d_in[5];
    const float* W_ukv   = (const float*)d_in[6];
    const float* kv_ln_g = (const float*)d_in[7];
    const float* kv_ln_b = (const float*)d_in[8];
    const float* preq_g  = (const float*)d_in[9];
    const float* preq_b  = (const float*)d_in[10];
    const float* prekv_g = (const float*)d_in[11];
    const float* prekv_b = (const float*)d_in[12];
    const float* wo      = (const float*)d_in[13];
    float* out = (float*)d_out;

    float *xq, *xkv, *t1, *cq, *Qp, *t2, *ckv, *KV, *ao;
    cudaGetSymbolAddress((void**)&xq,  g_xq);
    cudaGetSymbolAddress((void**)&xkv, g_xkv);
    cudaGetSymbolAddress((void**)&t1,  g_t1);
    cudaGetSymbolAddress((void**)&cq,  g_cq);
    cudaGetSymbolAddress((void**)&Qp,  g_Q);
    cudaGetSymbolAddress((void**)&t2,  g_t2);
    cudaGetSymbolAddress((void**)&ckv, g_ckv);
    cudaGetSymbolAddress((void**)&KV,  g_KV);
    cudaGetSymbolAddress((void**)&ao,  g_ao);

    // pre-norms
    ln_kernel<<<TOK, 256>>>(x, preq_g,  preq_b,  xq,  DM);
    ln_kernel<<<TOK, 256>>>(x, prekv_g, prekv_b, xkv, DM);

    // Q path
    sgemm_kernel<false><<<dim3(QPJ / 128, TOK / 128), 256>>>(xq, W_dq, t1, TOK, QPJ, DM, 1.0f);
    ln_kernel<<<TOK, 256>>>(t1, q_ln_g, q_ln_b, cq, QPJ);
    sgemm_kernel<false><<<dim3(DM / 128, TOK / 128), 256>>>(cq, W_uq, Qp, TOK, DM, QPJ, 0.125f);

    // KV path
    sgemm_kernel<false><<<dim3(DM / 128, TOK / 128), 256>>>(xkv, W_dkv, t2, TOK, DM, DM, 1.0f);
    ln_kernel<<<TOK, 256>>>(t2, kv_ln_g, kv_ln_b, ckv, DM);
    sgemm_kernel<false><<<dim3(2 * DM / 128, TOK / 128), 256>>>(ckv, W_ukv, KV, TOK, 2 * DM, DM, 1.0f);

    // attention
    int smem = 4 * 64 * 68 * (int)sizeof(float);
    cudaFuncSetAttribute(attn_kernel, cudaFuncAttributeMaxDynamicSharedMemorySize, smem);
    attn_kernel<<<dim3(SEQ / 64, NH, 2), 256, smem>>>(Qp, KV, ao);

    // output projection: ao @ wo^T
    sgemm_kernel<true><<<dim3(DM / 128, TOK / 128), 256>>>(ao, wo, out, TOK, DM, DM, 1.0f);
}

// round 5
// speedup vs baseline: 1.4343x; 1.4343x over previous
#include <cuda_runtime.h>
#include <math.h>

#define TOK 4096
#define DM 1024
#define QPJ 512
#define SEQ 2048
#define NH 16
#define DH 64

// -------- scratch (static device globals: allocation-free) --------
__device__ float g_xq [TOK * DM];
__device__ float g_xkv[TOK * DM];
__device__ float g_t1 [TOK * QPJ];
__device__ float g_cq [TOK * QPJ];
__device__ float g_Q  [TOK * DM];
__device__ float g_t2 [TOK * DM];
__device__ float g_ckv[TOK * DM];
__device__ float g_KV [TOK * 2 * DM];
__device__ float g_ao [TOK * DM];

// ------------------------- helpers -------------------------
__device__ __forceinline__ float to_tf32(float x) {
    float r;
    asm("cvt.rna.tf32.f32 %0, %1;" : "=f"(r) : "f"(x));
    return r;
}

__device__ __forceinline__ void mma_tf32(float c[4], const float a[4], const float b[2]) {
    asm volatile(
        "mma.sync.aligned.m16n8k8.row.col.f32.tf32.tf32.f32 "
        "{%0,%1,%2,%3}, {%4,%5,%6,%7}, {%8,%9}, {%0,%1,%2,%3};"
        : "+f"(c[0]), "+f"(c[1]), "+f"(c[2]), "+f"(c[3])
        : "r"(__float_as_uint(a[0])), "r"(__float_as_uint(a[1])),
          "r"(__float_as_uint(a[2])), "r"(__float_as_uint(a[3])),
          "r"(__float_as_uint(b[0])), "r"(__float_as_uint(b[1])));
}

// ------------------------- LayerNorm (float4) -------------------------
__global__ __launch_bounds__(256) void ln_kernel(
    const float* __restrict__ in, const float* __restrict__ gg,
    const float* __restrict__ bb, float* __restrict__ out, int D)
{
    int row = blockIdx.x;
    const float* x = in + (size_t)row * D;
    float* o = out + (size_t)row * D;
    int D4 = D >> 2;

    float s = 0.f, s2 = 0.f;
    float4 v = make_float4(0.f, 0.f, 0.f, 0.f);
    int i = threadIdx.x;
    if (i < D4) {
        v = ((const float4*)x)[i];
        s = v.x + v.y + v.z + v.w;
        s2 = v.x * v.x + v.y * v.y + v.z * v.z + v.w * v.w;
    }
    __shared__ float red[64];
    #pragma unroll
    for (int m = 16; m; m >>= 1) {
        s  += __shfl_xor_sync(0xffffffffu, s,  m);
        s2 += __shfl_xor_sync(0xffffffffu, s2, m);
    }
    int wid = threadIdx.x >> 5, lid = threadIdx.x & 31;
    if (lid == 0) { red[wid] = s; red[32 + wid] = s2; }
    __syncthreads();
    if (wid == 0) {
        s  = (lid < 8) ? red[lid]      : 0.f;
        s2 = (lid < 8) ? red[32 + lid] : 0.f;
        #pragma unroll
        for (int m = 4; m; m >>= 1) {
            s  += __shfl_xor_sync(0xffffffffu, s,  m);
            s2 += __shfl_xor_sync(0xffffffffu, s2, m);
        }
        if (lid == 0) { red[0] = s; red[1] = s2; }
    }
    __syncthreads();
    float mu  = red[0] / (float)D;
    float var = red[1] / (float)D - mu * mu;
    float r   = rsqrtf(var + 1e-5f);
    if (i < D4) {
        float4 g4 = ((const float4*)gg)[i];
        float4 b4 = ((const float4*)bb)[i];
        float4 w;
        w.x = (v.x - mu) * r * g4.x + b4.x;
        w.y = (v.y - mu) * r * g4.y + b4.y;
        w.z = (v.z - mu) * r * g4.z + b4.z;
        w.w = (v.w - mu) * r * g4.w + b4.w;
        ((float4*)o)[i] = w;
    }
}

// ------------------------- TF32 tensor-core GEMM -------------------------
// C[M,N] = scale * A[M,K] @ B    (TRANSB=0: B[K,N]; TRANSB=1: B[N,K] -> A@B^T)
// Block tile 128x128x32; 8 warps, each warp 64x32 via m16n8k8 tf32 mma.
// Smem: As[k][m] stride 136, Bs[k][n] stride 136 (stride%32==8 -> conflict-free frags)
#define SMST 136
template<bool TRANSB>
__global__ __launch_bounds__(256) void gemm_tf32(
    const float* __restrict__ A, const float* __restrict__ B,
    float* __restrict__ C, int M, int N, int K, float scale)
{
    __shared__ float As[32 * SMST];
    __shared__ float Bs[32 * SMST];

    int tid = threadIdx.x;
    int lane = tid & 31, warp = tid >> 5;
    int wm = warp >> 2, wn = warp & 3;          // warp grid 2x4
    int lr = lane >> 2, lq = lane & 3;
    int row0 = blockIdx.y * 128, col0 = blockIdx.x * 128;

    float acc[4][4][4];
    #pragma unroll
    for (int a = 0; a < 4; a++)
        #pragma unroll
        for (int b = 0; b < 4; b++)
            #pragma unroll
            for (int c = 0; c < 4; c++) acc[a][b][c] = 0.f;

    // global-load assignments
    int am  = tid & 127;          // A: m index (transposed store)
    int akh = tid >> 7;           // A: k half (0/1 -> k base 0/16)
    int bk  = tid >> 5;           // B non-trans: k row 0..7
    int bn4 = (tid & 31) * 4;     // B non-trans: n (float4)

    float4 aReg[4], bReg[4];

    // prefetch tile 0
    #pragma unroll
    for (int r = 0; r < 4; r++)
        aReg[r] = *(const float4*)&A[(size_t)(row0 + am) * K + akh * 16 + r * 4];
    if (TRANSB) {
        #pragma unroll
        for (int r = 0; r < 4; r++)
            bReg[r] = *(const float4*)&B[(size_t)(col0 + am) * K + akh * 16 + r * 4];
    } else {
        #pragma unroll
        for (int r = 0; r < 4; r++)
            bReg[r] = *(const float4*)&B[(size_t)(bk + r * 8) * N + col0 + bn4];
    }

    int nkt = K / 32;
    for (int t = 0; t < nkt; t++) {
        __syncthreads();
        // stage A (transposed, tf32-rounded)
        #pragma unroll
        for (int r = 0; r < 4; r++) {
            int kk = akh * 16 + r * 4;
            As[(kk + 0) * SMST + am] = to_tf32(aReg[r].x);
            As[(kk + 1) * SMST + am] = to_tf32(aReg[r].y);
            As[(kk + 2) * SMST + am] = to_tf32(aReg[r].z);
            As[(kk + 3) * SMST + am] = to_tf32(aReg[r].w);
        }
        // stage B
        if (TRANSB) {
            #pragma unroll
            for (int r = 0; r < 4; r++) {
                int kk = akh * 16 + r * 4;
                Bs[(kk + 0) * SMST + am] = to_tf32(bReg[r].x);
                Bs[(kk + 1) * SMST + am] = to_tf32(bReg[r].y);
                Bs[(kk + 2) * SMST + am] = to_tf32(bReg[r].z);
                Bs[(kk + 3) * SMST + am] = to_tf32(bReg[r].w);
            }
        } else {
            #pragma unroll
            for (int r = 0; r < 4; r++) {
                float4 w;
                w.x = to_tf32(bReg[r].x); w.y = to_tf32(bReg[r].y);
                w.z = to_tf32(bReg[r].z); w.w = to_tf32(bReg[r].w);
                *(float4*)&Bs[(bk + r * 8) * SMST + bn4] = w;
            }
        }
        __syncthreads();

        // prefetch next tile (overlaps with mma below)
        if (t + 1 < nkt) {
            int kt = (t + 1) * 32;
            #pragma unroll
            for (int r = 0; r < 4; r++)
                aReg[r] = *(const float4*)&A[(size_t)(row0 + am) * K + kt + akh * 16 + r * 4];
            if (TRANSB) {
                #pragma unroll
                for (int r = 0; r < 4; r++)
                    bReg[r] = *(const float4*)&B[(size_t)(col0 + am) * K + kt + akh * 16 + r * 4];
            } else {
                #pragma unroll
                for (int r = 0; r < 4; r++)
                    bReg[r] = *(const float4*)&B[(size_t)(kt + bk + r * 8) * N + col0 + bn4];
            }
        }

        // compute: 4 k-steps of 8
        #pragma unroll
        for (int ks = 0; ks < 4; ks++) {
            int k0 = ks * 8;
            float af[4][4], bf[4][2];
            #pragma unroll
            for (int mt = 0; mt < 4; mt++) {
                int m = wm * 64 + mt * 16 + lr;
                af[mt][0] = As[(k0 + lq) * SMST + m];
                af[mt][1] = As[(k0 + lq) * SMST + m + 8];
                af[mt][2] = As[(k0 + lq + 4) * SMST + m];
                af[mt][3] = As[(k0 + lq + 4) * SMST + m + 8];
            }
            #pragma unroll
            for (int nt = 0; nt < 4; nt++) {
                int n = wn * 32 + nt * 8 + lr;
                bf[nt][0] = Bs[(k0 + lq) * SMST + n];
                bf[nt][1] = Bs[(k0 + lq + 4) * SMST + n];
            }
            #pragma unroll
            for (int mt = 0; mt < 4; mt++)
                #pragma unroll
                for (int nt = 0; nt < 4; nt++)
                    mma_tf32(acc[mt][nt], af[mt], bf[nt]);
        }
    }

    // epilogue
    #pragma unroll
    for (int mt = 0; mt < 4; mt++) {
        #pragma unroll
        for (int nt = 0; nt < 4; nt++) {
            int r0 = row0 + wm * 64 + mt * 16 + lr;
            int c0 = col0 + wn * 32 + nt * 8 + lq * 2;
            float2 v0 = make_float2(acc[mt][nt][0] * scale, acc[mt][nt][1] * scale);
            float2 v1 = make_float2(acc[mt][nt][2] * scale, acc[mt][nt][3] * scale);
            *(float2*)&C[(size_t)r0 * N + c0]       = v0;
            *(float2*)&C[(size_t)(r0 + 8) * N + c0] = v1;
        }
    }
}

// ------------------------- Causal Flash Attention (fp32 SIMT) -------------------------
__global__ __launch_bounds__(256) void attn_kernel(
    const float* __restrict__ Q, const float* __restrict__ KV,
    float* __restrict__ O)
{
    extern __shared__ float sm[];
    float* Qt = sm;                  // [64][68]  Qt[d][r]
    float* Kt = sm + 64 * 68;        // [64][68]  Kt[d][c]
    float* Vs = sm + 2 * 64 * 68;    // [64][68]  Vs[k][d]
    float* Pt = sm + 3 * 64 * 68;    // [64][68]  Pt[k][r]

    int tid = threadIdx.x;
    int tx = tid & 15, ty = tid >> 4;
    int q0 = blockIdx.x * 64;
    int h  = blockIdx.y;
    int bb = blockIdx.z;

    #pragma unroll
    for (int rep = 0; rep < 4; rep++) {
        int idx = tid + rep * 256;
        int r  = idx >> 4;
        int d4 = (idx & 15) * 4;
        float4 v = *(const float4*)&Q[(size_t)(bb * SEQ + q0 + r) * DM + h * DH + d4];
        Qt[(d4 + 0) * 68 + r] = v.x;
        Qt[(d4 + 1) * 68 + r] = v.y;
        Qt[(d4 + 2) * 68 + r] = v.z;
        Qt[(d4 + 3) * 68 + r] = v.w;
    }

    float m_i[4], l_i[4], acc[4][4];
    #pragma unroll
    for (int i = 0; i < 4; i++) {
        m_i[i] = -INFINITY; l_i[i] = 0.f;
        #pragma unroll
        for (int j = 0; j < 4; j++) acc[i][j] = 0.f;
    }

    int ktiles = blockIdx.x + 1;
    for (int kt = 0; kt < ktiles; kt++) {
        int t0 = kt * 64;
        __syncthreads();
        #pragma unroll
        for (int rep = 0; rep < 4; rep++) {
            int idx = tid + rep * 256;
            int c  = idx >> 4;
            int d4 = (idx & 15) * 4;
            size_t tok = (size_t)(bb * SEQ + t0 + c);
            float4 k4 = *(const float4*)&KV[tok * 2048 + h * DH + d4];
            Kt[(d4 + 0) * 68 + c] = k4.x;
            Kt[(d4 + 1) * 68 + c] = k4.y;
            Kt[(d4 + 2) * 68 + c] = k4.z;
            Kt[(d4 + 3) * 68 + c] = k4.w;
            float4 v4 = *(const float4*)&KV[tok * 2048 + 1024 + h * DH + d4];
            *(float4*)&Vs[c * 68 + d4] = v4;
        }
        __syncthreads();

        float s[4][4];
        #pragma unroll
        for (int i = 0; i < 4; i++)
            #pragma unroll
            for (int j = 0; j < 4; j++) s[i][j] = 0.f;

        #pragma unroll 8
        for (int d = 0; d < 64; d++) {
            float4 q4 = *(const float4*)&Qt[d * 68 + ty * 4];
            float4 k4 = *(const float4*)&Kt[d * 68 + tx * 4];
            float qr[4] = {q4.x, q4.y, q4.z, q4.w};
            float kr[4] = {k4.x, k4.y, k4.z, k4.w};
            #pragma unroll
            for (int i = 0; i < 4; i++)
                #pragma unroll
                for (int j = 0; j < 4; j++)
                    s[i][j] = fmaf(qr[i], kr[j], s[i][j]);
        }

        if (kt == ktiles - 1) {
            #pragma unroll
            for (int i = 0; i < 4; i++)
                #pragma unroll
                for (int j = 0; j < 4; j++)
                    if (t0 + tx * 4 + j > q0 + ty * 4 + i) s[i][j] = -INFINITY;
        }

        #pragma unroll
        for (int i = 0; i < 4; i++) {
            float tm = fmaxf(fmaxf(s[i][0], s[i][1]), fmaxf(s[i][2], s[i][3]));
            #pragma unroll
            for (int m = 1; m < 16; m <<= 1)
                tm = fmaxf(tm, __shfl_xor_sync(0xffffffffu, tm, m));
            float mn = fmaxf(m_i[i], tm);
            float sc = __expf(m_i[i] - mn);
            m_i[i] = mn;
            float p[4], ps = 0.f;
            #pragma unroll
            for (int j = 0; j < 4; j++) { p[j] = __expf(s[i][j] - mn); ps += p[j]; }
            #pragma unroll
            for (int m = 1; m < 16; m <<= 1)
                ps += __shfl_xor_sync(0xffffffffu, ps, m);
            l_i[i] = l_i[i] * sc + ps;
            #pragma unroll
            for (int j = 0; j < 4; j++) {
                acc[i][j] *= sc;
                Pt[(tx * 4 + j) * 68 + ty * 4 + i] = p[j];
            }
        }
        __syncthreads();

        #pragma unroll 8
        for (int k = 0; k < 64; k++) {
            float4 p4 = *(const float4*)&Pt[k * 68 + ty * 4];
            float4 v4 = *(const float4*)&Vs[k * 68 + tx * 4];
            float pr[4] = {p4.x, p4.y, p4.z, p4.w};
            float vr[4] = {v4.x, v4.y, v4.z, v4.w};
            #pragma unroll
            for (int i = 0; i < 4; i++)
                #pragma unroll
                for (int j = 0; j < 4; j++)
                    acc[i][j] = fmaf(pr[i], vr[j], acc[i][j]);
        }
    }

    #pragma unroll
    for (int i = 0; i < 4; i++) {
        float inv = 1.f / l_i[i];
        size_t off = (size_t)(bb * SEQ + q0 + ty * 4 + i) * DM + h * DH + tx * 4;
        float4 v = make_float4(acc[i][0] * inv, acc[i][1] * inv,
                               acc[i][2] * inv, acc[i][3] * inv);
        *(float4*)&O[off] = v;
    }
}

// ------------------------- launch -------------------------
extern "C" void kernel_launch(void* const* d_in, const int* in_sizes, int n_in,
                              void* d_out, int out_size)
{
    (void)in_sizes; (void)n_in; (void)out_size;
    const float* x       = (const float*)d_in[0];
    const float* W_dq    = (const float*)d_in[1];
    const float* W_uq    = (const float*)d_in[2];
    const float* q_ln_g  = (const float*)d_in[3];
    const float* q_ln_b  = (const float*)d_in[4];
    const float* W_dkv   = (const float*)d_in[5];
    const float* W_ukv   = (const float*)d_in[6];
    const float* kv_ln_g = (const float*)d_in[7];
    const float* kv_ln_b = (const float*)d_in[8];
    const float* preq_g  = (const float*)d_in[9];
    const float* preq_b  = (const float*)d_in[10];
    const float* prekv_g = (const float*)d_in[11];
    const float* prekv_b = (const float*)d_in[12];
    const float* wo      = (const float*)d_in[13];
    float* out = (float*)d_out;

    float *xq, *xkv, *t1, *cq, *Qp, *t2, *ckv, *KV, *ao;
    cudaGetSymbolAddress((void**)&xq,  g_xq);
    cudaGetSymbolAddress((void**)&xkv, g_xkv);
    cudaGetSymbolAddress((void**)&t1,  g_t1);
    cudaGetSymbolAddress((void**)&cq,  g_cq);
    cudaGetSymbolAddress((void**)&Qp,  g_Q);
    cudaGetSymbolAddress((void**)&t2,  g_t2);
    cudaGetSymbolAddress((void**)&ckv, g_ckv);
    cudaGetSymbolAddress((void**)&KV,  g_KV);
    cudaGetSymbolAddress((void**)&ao,  g_ao);

    // pre-norms
    ln_kernel<<<TOK, 256>>>(x, preq_g,  preq_b,  xq,  DM);
    ln_kernel<<<TOK, 256>>>(x, prekv_g, prekv_b, xkv, DM);

    // Q path
    gemm_tf32<false><<<dim3(QPJ / 128, TOK / 128), 256>>>(xq, W_dq, t1, TOK, QPJ, DM, 1.0f);
    ln_kernel<<<TOK, 256>>>(t1, q_ln_g, q_ln_b, cq, QPJ);
    gemm_tf32<false><<<dim3(DM / 128, TOK / 128), 256>>>(cq, W_uq, Qp, TOK, DM, QPJ, 0.125f);

    // KV path
    gemm_tf32<false><<<dim3(DM / 128, TOK / 128), 256>>>(xkv, W_dkv, t2, TOK, DM, DM, 1.0f);
    ln_kernel<<<TOK, 256>>>(t2, kv_ln_g, kv_ln_b, ckv, DM);
    gemm_tf32<false><<<dim3(2 * DM / 128, TOK / 128), 256>>>(ckv, W_ukv, KV, TOK, 2 * DM, DM, 1.0f);

    // attention
    int smem = 4 * 64 * 68 * (int)sizeof(float);
    cudaFuncSetAttribute(attn_kernel, cudaFuncAttributeMaxDynamicSharedMemorySize, smem);
    attn_kernel<<<dim3(SEQ / 64, NH, 2), 256, smem>>>(Qp, KV, ao);

    // output projection: ao @ wo^T
    gemm_tf32<true><<<dim3(DM / 128, TOK / 128), 256>>>(ao, wo, out, TOK, DM, DM, 1.0f);
}

// round 6
// speedup vs baseline: 1.6537x; 1.1530x over previous
#include <cuda_runtime.h>
#include <math.h>

#define TOK 4096
#define DM 1024
#define QPJ 512
#define SEQ 2048
#define NH 16
#define DH 64

// -------- scratch (static device globals: allocation-free) --------
__device__ float g_xq [TOK * DM];
__device__ float g_xkv[TOK * DM];
__device__ float g_t1 [TOK * QPJ];
__device__ float g_cq [TOK * QPJ];
__device__ float g_Q  [TOK * DM];
__device__ float g_t2 [TOK * DM];
__device__ float g_ckv[TOK * DM];
__device__ float g_KV [TOK * 2 * DM];
__device__ float g_ao [TOK * DM];

// ------------------------- helpers -------------------------
__device__ __forceinline__ float to_tf32(float x) {
    float r;
    asm("cvt.rna.tf32.f32 %0, %1;" : "=f"(r) : "f"(x));
    return r;
}

__device__ __forceinline__ void mma_tf32(float c[4], const float a[4], const float b[2]) {
    asm volatile(
        "mma.sync.aligned.m16n8k8.row.col.f32.tf32.tf32.f32 "
        "{%0,%1,%2,%3}, {%4,%5,%6,%7}, {%8,%9}, {%0,%1,%2,%3};"
        : "+f"(c[0]), "+f"(c[1]), "+f"(c[2]), "+f"(c[3])
        : "r"(__float_as_uint(a[0])), "r"(__float_as_uint(a[1])),
          "r"(__float_as_uint(a[2])), "r"(__float_as_uint(a[3])),
          "r"(__float_as_uint(b[0])), "r"(__float_as_uint(b[1])));
}

// ------------------------- LayerNorm (float4) -------------------------
__global__ __launch_bounds__(256) void ln_kernel(
    const float* __restrict__ in, const float* __restrict__ gg,
    const float* __restrict__ bb, float* __restrict__ out, int D)
{
    int row = blockIdx.x;
    const float* x = in + (size_t)row * D;
    float* o = out + (size_t)row * D;
    int D4 = D >> 2;

    float s = 0.f, s2 = 0.f;
    float4 v = make_float4(0.f, 0.f, 0.f, 0.f);
    int i = threadIdx.x;
    if (i < D4) {
        v = ((const float4*)x)[i];
        s = v.x + v.y + v.z + v.w;
        s2 = v.x * v.x + v.y * v.y + v.z * v.z + v.w * v.w;
    }
    __shared__ float red[64];
    #pragma unroll
    for (int m = 16; m; m >>= 1) {
        s  += __shfl_xor_sync(0xffffffffu, s,  m);
        s2 += __shfl_xor_sync(0xffffffffu, s2, m);
    }
    int wid = threadIdx.x >> 5, lid = threadIdx.x & 31;
    if (lid == 0) { red[wid] = s; red[32 + wid] = s2; }
    __syncthreads();
    if (wid == 0) {
        s  = (lid < 8) ? red[lid]      : 0.f;
        s2 = (lid < 8) ? red[32 + lid] : 0.f;
        #pragma unroll
        for (int m = 4; m; m >>= 1) {
            s  += __shfl_xor_sync(0xffffffffu, s,  m);
            s2 += __shfl_xor_sync(0xffffffffu, s2, m);
        }
        if (lid == 0) { red[0] = s; red[1] = s2; }
    }
    __syncthreads();
    float mu  = red[0] / (float)D;
    float var = red[1] / (float)D - mu * mu;
    float r   = rsqrtf(var + 1e-5f);
    if (i < D4) {
        float4 g4 = ((const float4*)gg)[i];
        float4 b4 = ((const float4*)bb)[i];
        float4 w;
        w.x = (v.x - mu) * r * g4.x + b4.x;
        w.y = (v.y - mu) * r * g4.y + b4.y;
        w.z = (v.z - mu) * r * g4.z + b4.z;
        w.w = (v.w - mu) * r * g4.w + b4.w;
        ((float4*)o)[i] = w;
    }
}

// ------------------------- TF32 tensor-core GEMM -------------------------
#define SMST 136
template<bool TRANSB>
__global__ __launch_bounds__(256) void gemm_tf32(
    const float* __restrict__ A, const float* __restrict__ B,
    float* __restrict__ C, int M, int N, int K, float scale)
{
    __shared__ float As[32 * SMST];
    __shared__ float Bs[32 * SMST];

    int tid = threadIdx.x;
    int lane = tid & 31, warp = tid >> 5;
    int wm = warp >> 2, wn = warp & 3;
    int lr = lane >> 2, lq = lane & 3;
    int row0 = blockIdx.y * 128, col0 = blockIdx.x * 128;

    float acc[4][4][4];
    #pragma unroll
    for (int a = 0; a < 4; a++)
        #pragma unroll
        for (int b = 0; b < 4; b++)
            #pragma unroll
            for (int c = 0; c < 4; c++) acc[a][b][c] = 0.f;

    int am  = tid & 127;
    int akh = tid >> 7;
    int bk  = tid >> 5;
    int bn4 = (tid & 31) * 4;

    float4 aReg[4], bReg[4];

    #pragma unroll
    for (int r = 0; r < 4; r++)
        aReg[r] = *(const float4*)&A[(size_t)(row0 + am) * K + akh * 16 + r * 4];
    if (TRANSB) {
        #pragma unroll
        for (int r = 0; r < 4; r++)
            bReg[r] = *(const float4*)&B[(size_t)(col0 + am) * K + akh * 16 + r * 4];
    } else {
        #pragma unroll
        for (int r = 0; r < 4; r++)
            bReg[r] = *(const float4*)&B[(size_t)(bk + r * 8) * N + col0 + bn4];
    }

    int nkt = K / 32;
    for (int t = 0; t < nkt; t++) {
        __syncthreads();
        #pragma unroll
        for (int r = 0; r < 4; r++) {
            int kk = akh * 16 + r * 4;
            As[(kk + 0) * SMST + am] = to_tf32(aReg[r].x);
            As[(kk + 1) * SMST + am] = to_tf32(aReg[r].y);
            As[(kk + 2) * SMST + am] = to_tf32(aReg[r].z);
            As[(kk + 3) * SMST + am] = to_tf32(aReg[r].w);
        }
        if (TRANSB) {
            #pragma unroll
            for (int r = 0; r < 4; r++) {
                int kk = akh * 16 + r * 4;
                Bs[(kk + 0) * SMST + am] = to_tf32(bReg[r].x);
                Bs[(kk + 1) * SMST + am] = to_tf32(bReg[r].y);
                Bs[(kk + 2) * SMST + am] = to_tf32(bReg[r].z);
                Bs[(kk + 3) * SMST + am] = to_tf32(bReg[r].w);
            }
        } else {
            #pragma unroll
            for (int r = 0; r < 4; r++) {
                float4 w;
                w.x = to_tf32(bReg[r].x); w.y = to_tf32(bReg[r].y);
                w.z = to_tf32(bReg[r].z); w.w = to_tf32(bReg[r].w);
                *(float4*)&Bs[(bk + r * 8) * SMST + bn4] = w;
            }
        }
        __syncthreads();

        if (t + 1 < nkt) {
            int kt = (t + 1) * 32;
            #pragma unroll
            for (int r = 0; r < 4; r++)
                aReg[r] = *(const float4*)&A[(size_t)(row0 + am) * K + kt + akh * 16 + r * 4];
            if (TRANSB) {
                #pragma unroll
                for (int r = 0; r < 4; r++)
                    bReg[r] = *(const float4*)&B[(size_t)(col0 + am) * K + kt + akh * 16 + r * 4];
            } else {
                #pragma unroll
                for (int r = 0; r < 4; r++)
                    bReg[r] = *(const float4*)&B[(size_t)(kt + bk + r * 8) * N + col0 + bn4];
            }
        }

        #pragma unroll
        for (int ks = 0; ks < 4; ks++) {
            int k0 = ks * 8;
            float af[4][4], bf[4][2];
            #pragma unroll
            for (int mt = 0; mt < 4; mt++) {
                int m = wm * 64 + mt * 16 + lr;
                af[mt][0] = As[(k0 + lq) * SMST + m];
                af[mt][1] = As[(k0 + lq) * SMST + m + 8];
                af[mt][2] = As[(k0 + lq + 4) * SMST + m];
                af[mt][3] = As[(k0 + lq + 4) * SMST + m + 8];
            }
            #pragma unroll
            for (int nt = 0; nt < 4; nt++) {
                int n = wn * 32 + nt * 8 + lr;
                bf[nt][0] = Bs[(k0 + lq) * SMST + n];
                bf[nt][1] = Bs[(k0 + lq + 4) * SMST + n];
            }
            #pragma unroll
            for (int mt = 0; mt < 4; mt++)
                #pragma unroll
                for (int nt = 0; nt < 4; nt++)
                    mma_tf32(acc[mt][nt], af[mt], bf[nt]);
        }
    }

    #pragma unroll
    for (int mt = 0; mt < 4; mt++) {
        #pragma unroll
        for (int nt = 0; nt < 4; nt++) {
            int r0 = row0 + wm * 64 + mt * 16 + lr;
            int c0 = col0 + wn * 32 + nt * 8 + lq * 2;
            float2 v0 = make_float2(acc[mt][nt][0] * scale, acc[mt][nt][1] * scale);
            float2 v1 = make_float2(acc[mt][nt][2] * scale, acc[mt][nt][3] * scale);
            *(float2*)&C[(size_t)r0 * N + c0]       = v0;
            *(float2*)&C[(size_t)(r0 + 8) * N + c0] = v1;
        }
    }
}

// ------------------------- Tensor-core Causal Flash Attention -------------------------
// 128 q-rows per block, 8 warps (16 rows each), k-tiles of 64, split-tf32 mma.
// Smem: K row-major [c][d] stride 76, V row-major [k][d] stride 72,
//       P/Q staging [m][k] stride 76. Fragments split hi/lo in registers.
#define BQ 128
#define BK 64
#define KS_ST 76
#define VS_ST 72
#define PS_ST 76

__global__ __launch_bounds__(256) void attn_mma(
    const float* __restrict__ Q, const float* __restrict__ KV,
    float* __restrict__ O)
{
    extern __shared__ float sm[];
    float* Ks = sm;                       // [64][76]
    float* Vs = Ks + BK * KS_ST;          // [64][72]
    float* Ps = Vs + BK * VS_ST;          // [128][76]  (Q staging, then P)

    int tid  = threadIdx.x;
    int lane = tid & 31, warp = tid >> 5;
    int lr = lane >> 2, lq = lane & 3;
    int qt = gridDim.x - 1 - blockIdx.x;   // heavy tiles first
    int q0 = qt * BQ;
    int h  = blockIdx.y;
    int bb = blockIdx.z;
    int wrow = warp * 16;

    // ---- stage Q tile into Ps, then cache pre-split fragments in regs ----
    #pragma unroll
    for (int rep = 0; rep < 8; rep++) {
        int idx = tid + rep * 256;
        int r  = idx >> 4;
        int d4 = (idx & 15) * 4;
        float4 v = *(const float4*)&Q[(size_t)(bb * SEQ + q0 + r) * DM + h * DH + d4];
        *(float4*)&Ps[r * PS_ST + d4] = v;
    }
    __syncthreads();

    float qh[8][4], ql[8][4];
    #pragma unroll
    for (int ks = 0; ks < 8; ks++) {
        int base = (wrow + lr) * PS_ST + ks * 8 + lq;
        float f[4];
        f[0] = Ps[base];
        f[1] = Ps[base + 8 * PS_ST];
        f[2] = Ps[base + 4];
        f[3] = Ps[base + 8 * PS_ST + 4];
        #pragma unroll
        for (int i = 0; i < 4; i++) {
            qh[ks][i] = to_tf32(f[i]);
            ql[ks][i] = to_tf32(f[i] - qh[ks][i]);
        }
    }

    float m0 = -INFINITY, m1 = -INFINITY, l0 = 0.f, l1 = 0.f;
    float acc[8][4];
    #pragma unroll
    for (int nt = 0; nt < 8; nt++)
        #pragma unroll
        for (int i = 0; i < 4; i++) acc[nt][i] = 0.f;

    int ktiles = 2 * qt + 2;
    for (int kt = 0; kt < ktiles; kt++) {
        int t0 = kt * BK;
        __syncthreads();   // Ks/Vs free, qf reads done (iter 0)
        #pragma unroll
        for (int rep = 0; rep < 4; rep++) {
            int idx = tid + rep * 256;
            int c  = idx >> 4;
            int d4 = (idx & 15) * 4;
            size_t toff = (size_t)(bb * SEQ + t0 + c) * 2048 + h * DH + d4;
            *(float4*)&Ks[c * KS_ST + d4] = *(const float4*)&KV[toff];
            *(float4*)&Vs[c * VS_ST + d4] = *(const float4*)&KV[toff + 1024];
        }
        __syncthreads();

        // ---- scores S = Q K^T (split-tf32: 3 mma per step) ----
        float s[8][4];
        #pragma unroll
        for (int nt = 0; nt < 8; nt++)
            #pragma unroll
            for (int i = 0; i < 4; i++) s[nt][i] = 0.f;

        #pragma unroll
        for (int ks = 0; ks < 8; ks++) {
            #pragma unroll
            for (int nt = 0; nt < 8; nt++) {
                int ad = (nt * 8 + lr) * KS_ST + ks * 8 + lq;
                float b0 = Ks[ad], b1 = Ks[ad + 4];
                float bh[2], bl[2];
                bh[0] = to_tf32(b0); bl[0] = to_tf32(b0 - bh[0]);
                bh[1] = to_tf32(b1); bl[1] = to_tf32(b1 - bh[1]);
                mma_tf32(s[nt], qh[ks], bh);
                mma_tf32(s[nt], qh[ks], bl);
                mma_tf32(s[nt], ql[ks], bh);
            }
        }

        // ---- causal mask (last two tiles only) ----
        if (kt >= ktiles - 2) {
            int r0 = q0 + wrow + lr;
            #pragma unroll
            for (int nt = 0; nt < 8; nt++) {
                int c0 = t0 + nt * 8 + 2 * lq;
                if (c0     > r0)     s[nt][0] = -INFINITY;
                if (c0 + 1 > r0)     s[nt][1] = -INFINITY;
                if (c0     > r0 + 8) s[nt][2] = -INFINITY;
                if (c0 + 1 > r0 + 8) s[nt][3] = -INFINITY;
            }
        }

        // ---- online softmax (rows lr and lr+8, quad reduction) ----
        float rx0 = -INFINITY, rx1 = -INFINITY;
        #pragma unroll
        for (int nt = 0; nt < 8; nt++) {
            rx0 = fmaxf(rx0, fmaxf(s[nt][0], s[nt][1]));
            rx1 = fmaxf(rx1, fmaxf(s[nt][2], s[nt][3]));
        }
        rx0 = fmaxf(rx0, __shfl_xor_sync(0xffffffffu, rx0, 1));
        rx0 = fmaxf(rx0, __shfl_xor_sync(0xffffffffu, rx0, 2));
        rx1 = fmaxf(rx1, __shfl_xor_sync(0xffffffffu, rx1, 1));
        rx1 = fmaxf(rx1, __shfl_xor_sync(0xffffffffu, rx1, 2));

        float mn0 = fmaxf(m0, rx0), mn1 = fmaxf(m1, rx1);
        float sc0 = __expf(m0 - mn0), sc1 = __expf(m1 - mn1);
        m0 = mn0; m1 = mn1;

        float sum0 = 0.f, sum1 = 0.f;
        #pragma unroll
        for (int nt = 0; nt < 8; nt++) {
            float p0 = __expf(s[nt][0] - mn0);
            float p1 = __expf(s[nt][1] - mn0);
            float p2 = __expf(s[nt][2] - mn1);
            float p3 = __expf(s[nt][3] - mn1);
            sum0 += p0 + p1; sum1 += p2 + p3;
            int ad = (wrow + lr) * PS_ST + t0 % 1 * 0 + nt * 8 + 2 * lq; // base row
            *(float2*)&Ps[ad]              = make_float2(p0, p1);
            *(float2*)&Ps[ad + 8 * PS_ST]  = make_float2(p2, p3);
            acc[nt][0] *= sc0; acc[nt][1] *= sc0;
            acc[nt][2] *= sc1; acc[nt][3] *= sc1;
        }
        sum0 += __shfl_xor_sync(0xffffffffu, sum0, 1);
        sum0 += __shfl_xor_sync(0xffffffffu, sum0, 2);
        sum1 += __shfl_xor_sync(0xffffffffu, sum1, 1);
        sum1 += __shfl_xor_sync(0xffffffffu, sum1, 2);
        l0 = l0 * sc0 + sum0;
        l1 = l1 * sc1 + sum1;

        __syncwarp();   // P rows are warp-private; warp-level visibility only

        // ---- O += P V (split-tf32) ----
        #pragma unroll
        for (int ks = 0; ks < 8; ks++) {
            int base = (wrow + lr) * PS_ST + ks * 8 + lq;
            float f[4];
            f[0] = Ps[base];
            f[1] = Ps[base + 8 * PS_ST];
            f[2] = Ps[base + 4];
            f[3] = Ps[base + 8 * PS_ST + 4];
            float ah[4], al[4];
            #pragma unroll
            for (int i = 0; i < 4; i++) {
                ah[i] = to_tf32(f[i]);
                al[i] = to_tf32(f[i] - ah[i]);
            }
            #pragma unroll
            for (int nt = 0; nt < 8; nt++) {
                int vd = (ks * 8 + lq) * VS_ST + nt * 8 + lr;
                float b0 = Vs[vd], b1 = Vs[vd + 4 * VS_ST];
                float vh[2], vl[2];
                vh[0] = to_tf32(b0); vl[0] = to_tf32(b0 - vh[0]);
                vh[1] = to_tf32(b1); vl[1] = to_tf32(b1 - vh[1]);
                mma_tf32(acc[nt], ah, vh);
                mma_tf32(acc[nt], ah, vl);
                mma_tf32(acc[nt], al, vh);
            }
        }
    }

    // ---- epilogue ----
    float inv0 = 1.f / l0, inv1 = 1.f / l1;
    size_t row0 = (size_t)(bb * SEQ + q0 + wrow + lr);
    #pragma unroll
    for (int nt = 0; nt < 8; nt++) {
        int col = h * DH + nt * 8 + 2 * lq;
        *(float2*)&O[row0 * DM + col] =
            make_float2(acc[nt][0] * inv0, acc[nt][1] * inv0);
        *(float2*)&O[(row0 + 8) * DM + col] =
            make_float2(acc[nt][2] * inv1, acc[nt][3] * inv1);
    }
}

// ------------------------- launch -------------------------
extern "C" void kernel_launch(void* const* d_in, const int* in_sizes, int n_in,
                              void* d_out, int out_size)
{
    (void)in_sizes; (void)n_in; (void)out_size;
    const float* x       = (const float*)d_in[0];
    const float* W_dq    = (const float*)d_in[1];
    const float* W_uq    = (const float*)d_in[2];
    const float* q_ln_g  = (const float*)d_in[3];
    const float* q_ln_b  = (const float*)d_in[4];
    const float* W_dkv   = (const float*)d_in[5];
    const float* W_ukv   = (const float*)d_in[6];
    const float* kv_ln_g = (const float*)d_in[7];
    const float* kv_ln_b = (const float*)d_in[8];
    const float* preq_g  = (const float*)d_in[9];
    const float* preq_b  = (const float*)d_in[10];
    const float* prekv_g = (const float*)d_in[11];
    const float* prekv_b = (const float*)d_in[12];
    const float* wo      = (const float*)d_in[13];
    float* out = (float*)d_out;

    float *xq, *xkv, *t1, *cq, *Qp, *t2, *ckv, *KV, *ao;
    cudaGetSymbolAddress((void**)&xq,  g_xq);
    cudaGetSymbolAddress((void**)&xkv, g_xkv);
    cudaGetSymbolAddress((void**)&t1,  g_t1);
    cudaGetSymbolAddress((void**)&cq,  g_cq);
    cudaGetSymbolAddress((void**)&Qp,  g_Q);
    cudaGetSymbolAddress((void**)&t2,  g_t2);
    cudaGetSymbolAddress((void**)&ckv, g_ckv);
    cudaGetSymbolAddress((void**)&KV,  g_KV);
    cudaGetSymbolAddress((void**)&ao,  g_ao);

    // pre-norms
    ln_kernel<<<TOK, 256>>>(x, preq_g,  preq_b,  xq,  DM);
    ln_kernel<<<TOK, 256>>>(x, prekv_g, prekv_b, xkv, DM);

    // Q path
    gemm_tf32<false><<<dim3(QPJ / 128, TOK / 128), 256>>>(xq, W_dq, t1, TOK, QPJ, DM, 1.0f);
    ln_kernel<<<TOK, 256>>>(t1, q_ln_g, q_ln_b, cq, QPJ);
    gemm_tf32<false><<<dim3(DM / 128, TOK / 128), 256>>>(cq, W_uq, Qp, TOK, DM, QPJ, 0.125f);

    // KV path
    gemm_tf32<false><<<dim3(DM / 128, TOK / 128), 256>>>(xkv, W_dkv, t2, TOK, DM, DM, 1.0f);
    ln_kernel<<<TOK, 256>>>(t2, kv_ln_g, kv_ln_b, ckv, DM);
    gemm_tf32<false><<<dim3(2 * DM / 128, TOK / 128), 256>>>(ckv, W_ukv, KV, TOK, 2 * DM, DM, 1.0f);

    // attention (tensor-core flash, split-tf32)
    int smem = (BK * KS_ST + BK * VS_ST + BQ * PS_ST) * (int)sizeof(float);
    cudaFuncSetAttribute(attn_mma, cudaFuncAttributeMaxDynamicSharedMemorySize, smem);
    attn_mma<<<dim3(SEQ / BQ, NH, 2), 256, smem>>>(Qp, KV, ao);

    // output projection: ao @ wo^T
    gemm_tf32<true><<<dim3(DM / 128, TOK / 128), 256>>>(ao, wo, out, TOK, DM, DM, 1.0f);
}

// round 8
// speedup vs baseline: 1.7361x; 1.0498x over previous
#include <cuda_runtime.h>
#include <math.h>

#define TOK 4096
#define DM 1024
#define QPJ 512
#define SEQ 2048
#define NH 16
#define DH 64

// -------- scratch (static device globals: allocation-free) --------
__device__ float g_xq [TOK * DM];
__device__ float g_xkv[TOK * DM];
__device__ float g_t1 [TOK * QPJ];
__device__ float g_cq [TOK * QPJ];
__device__ float g_Q  [TOK * DM];
__device__ float g_t2 [TOK * DM];
__device__ float g_ckv[TOK * DM];
__device__ float g_KV [TOK * 2 * DM];
__device__ float g_ao [TOK * DM];

// ------------------------- helpers -------------------------
__device__ __forceinline__ float to_tf32(float x) {
    float r;
    asm("cvt.rna.tf32.f32 %0, %1;" : "=f"(r) : "f"(x));
    return r;
}

__device__ __forceinline__ void mma_tf32(float c[4], const float a[4], const float b[2]) {
    asm volatile(
        "mma.sync.aligned.m16n8k8.row.col.f32.tf32.tf32.f32 "
        "{%0,%1,%2,%3}, {%4,%5,%6,%7}, {%8,%9}, {%0,%1,%2,%3};"
        : "+f"(c[0]), "+f"(c[1]), "+f"(c[2]), "+f"(c[3])
        : "r"(__float_as_uint(a[0])), "r"(__float_as_uint(a[1])),
          "r"(__float_as_uint(a[2])), "r"(__float_as_uint(a[3])),
          "r"(__float_as_uint(b[0])), "r"(__float_as_uint(b[1])));
}

__device__ __forceinline__ void cpa16(float* dst, const float* src) {
    unsigned d = (unsigned)__cvta_generic_to_shared(dst);
    asm volatile("cp.async.cg.shared.global [%0], [%1], 16;\n" :: "r"(d), "l"(src));
}
#define CP_COMMIT() asm volatile("cp.async.commit_group;\n")
#define CP_WAIT1()  asm volatile("cp.async.wait_group 1;\n")
#define CP_WAIT0()  asm volatile("cp.async.wait_group 0;\n")

// ------------------------- fused dual LayerNorm -------------------------
// grid (rows, 2): blockIdx.y selects parameter set.
__global__ __launch_bounds__(256) void ln2_kernel(
    const float* __restrict__ in0, const float* __restrict__ g0,
    const float* __restrict__ b0, float* __restrict__ o0, int D0,
    const float* __restrict__ in1, const float* __restrict__ g1,
    const float* __restrict__ b1, float* __restrict__ o1, int D1)
{
    const float* in = blockIdx.y ? in1 : in0;
    const float* gg = blockIdx.y ? g1  : g0;
    const float* bb = blockIdx.y ? b1  : b0;
    float* out      = blockIdx.y ? o1  : o0;
    int D           = blockIdx.y ? D1  : D0;

    int row = blockIdx.x;
    const float* x = in + (size_t)row * D;
    float* o = out + (size_t)row * D;
    int D4 = D >> 2;

    float s = 0.f, s2 = 0.f;
    float4 v = make_float4(0.f, 0.f, 0.f, 0.f);
    int i = threadIdx.x;
    if (i < D4) {
        v = ((const float4*)x)[i];
        s = v.x + v.y + v.z + v.w;
        s2 = v.x * v.x + v.y * v.y + v.z * v.z + v.w * v.w;
    }
    __shared__ float red[64];
    #pragma unroll
    for (int m = 16; m; m >>= 1) {
        s  += __shfl_xor_sync(0xffffffffu, s,  m);
        s2 += __shfl_xor_sync(0xffffffffu, s2, m);
    }
    int wid = threadIdx.x >> 5, lid = threadIdx.x & 31;
    if (lid == 0) { red[wid] = s; red[32 + wid] = s2; }
    __syncthreads();
    if (wid == 0) {
        s  = (lid < 8) ? red[lid]      : 0.f;
        s2 = (lid < 8) ? red[32 + lid] : 0.f;
        #pragma unroll
        for (int m = 4; m; m >>= 1) {
            s  += __shfl_xor_sync(0xffffffffu, s,  m);
            s2 += __shfl_xor_sync(0xffffffffu, s2, m);
        }
        if (lid == 0) { red[0] = s; red[1] = s2; }
    }
    __syncthreads();
    float mu  = red[0] / (float)D;
    float var = red[1] / (float)D - mu * mu;
    float r   = rsqrtf(var + 1e-5f);
    if (i < D4) {
        float4 g4 = ((const float4*)gg)[i];
        float4 b4 = ((const float4*)bb)[i];
        float4 w;
        w.x = (v.x - mu) * r * g4.x + b4.x;
        w.y = (v.y - mu) * r * g4.y + b4.y;
        w.z = (v.z - mu) * r * g4.z + b4.z;
        w.w = (v.w - mu) * r * g4.w + b4.w;
        ((float4*)o)[i] = w;
    }
}

// ------------------- grouped cp.async double-buffered TF32 GEMM -------------------
// Per group g (blockIdx.z): C = scale * A[4096,K] @ B  (TRANSB=0: B[K,N]; 1: B[N,K])
// Block tile 128x128x32, 8 warps (2x4), double-buffered cp.async, tf32 at frag load.
// Smem: A [m][k] stride 36; B: TRANSB=0 -> [k][n] stride 136, TRANSB=1 -> [n][k] stride 36.
#define AST 36
#define BST 136
#define ASZ (128 * AST)

template<bool TRANSB>
__global__ __launch_bounds__(256) void gemm_tf32_g(
    const float* __restrict__ A0, const float* __restrict__ B0, float* __restrict__ C0,
    int N0, int K0, float s0,
    const float* __restrict__ A1, const float* __restrict__ B1, float* __restrict__ C1,
    int N1, int K1, float s1)
{
    const float* A = blockIdx.z ? A1 : A0;
    const float* B = blockIdx.z ? B1 : B0;
    float* C       = blockIdx.z ? C1 : C0;
    int N          = blockIdx.z ? N1 : N0;
    int K          = blockIdx.z ? K1 : K0;
    float scale    = blockIdx.z ? s1 : s0;

    int col0 = blockIdx.x * 128;
    if (col0 >= N) return;
    int row0 = blockIdx.y * 128;

    extern __shared__ float gsm[];
    const int BSZ = TRANSB ? (128 * AST) : (32 * BST);
    float* Asm[2] = { gsm, gsm + ASZ };
    float* Bsm[2] = { gsm + 2 * ASZ, gsm + 2 * ASZ + BSZ };

    int tid = threadIdx.x;
    int lane = tid & 31, warp = tid >> 5;
    int wm = warp >> 2, wn = warp & 3;
    int lr = lane >> 2, lq = lane & 3;

    float acc[4][4][4];
    #pragma unroll
    for (int a = 0; a < 4; a++)
        #pragma unroll
        for (int b = 0; b < 4; b++)
            #pragma unroll
            for (int c = 0; c < 4; c++) acc[a][b][c] = 0.f;

    // load index assignments
    int ar = tid >> 1;              // A row 0..127 (also B row for TRANSB=1)
    int ac = (tid & 1) * 4;         // A float4 col base (0 or 4) in 8-float4 row
    int bk = tid >> 3;              // B k-row 0..31 (TRANSB=0)
    int bj = tid & 7;               // B float4 lane (TRANSB=0)

    auto load_tile = [&](int st, int kt) {
        #pragma unroll
        for (int r = 0; r < 4; r++)
            cpa16(&Asm[st][ar * AST + (ac + r) * 4],
                  &A[(size_t)(row0 + ar) * K + kt + (ac + r) * 4]);
        if (TRANSB) {
            #pragma unroll
            for (int r = 0; r < 4; r++)
                cpa16(&Bsm[st][ar * AST + (ac + r) * 4],
                      &B[(size_t)(col0 + ar) * K + kt + (ac + r) * 4]);
        } else {
            #pragma unroll
            for (int r = 0; r < 4; r++)
                cpa16(&Bsm[st][bk * BST + (bj + r * 8) * 4],
                      &B[(size_t)(kt + bk) * N + col0 + (bj + r * 8) * 4]);
        }
    };

    int nkt = K / 32;
    load_tile(0, 0);
    CP_COMMIT();

    for (int t = 0; t < nkt; t++) {
        if (t + 1 < nkt) {
            load_tile((t + 1) & 1, (t + 1) * 32);
            CP_COMMIT();
            CP_WAIT1();
        } else {
            CP_WAIT0();
        }
        __syncthreads();

        const float* As = Asm[t & 1];
        const float* Bs = Bsm[t & 1];
        #pragma unroll
        for (int ks = 0; ks < 4; ks++) {
            int k0 = ks * 8;
            float af[4][4], bf[4][2];
            #pragma unroll
            for (int mt = 0; mt < 4; mt++) {
                int m = wm * 64 + mt * 16 + lr;
                af[mt][0] = to_tf32(As[m * AST + k0 + lq]);
                af[mt][1] = to_tf32(As[(m + 8) * AST + k0 + lq]);
                af[mt][2] = to_tf32(As[m * AST + k0 + lq + 4]);
                af[mt][3] = to_tf32(As[(m + 8) * AST + k0 + lq + 4]);
            }
            #pragma unroll
            for (int nt = 0; nt < 4; nt++) {
                int n = wn * 32 + nt * 8 + lr;
                if (TRANSB) {
                    bf[nt][0] = to_tf32(Bs[n * AST + k0 + lq]);
                    bf[nt][1] = to_tf32(Bs[n * AST + k0 + lq + 4]);
                } else {
                    bf[nt][0] = to_tf32(Bs[(k0 + lq) * BST + n]);
                    bf[nt][1] = to_tf32(Bs[(k0 + lq + 4) * BST + n]);
                }
            }
            #pragma unroll
            for (int mt = 0; mt < 4; mt++)
                #pragma unroll
                for (int nt = 0; nt < 4; nt++)
                    mma_tf32(acc[mt][nt], af[mt], bf[nt]);
        }
        __syncthreads();
    }

    #pragma unroll
    for (int mt = 0; mt < 4; mt++) {
        #pragma unroll
        for (int nt = 0; nt < 4; nt++) {
            int r0 = row0 + wm * 64 + mt * 16 + lr;
            int c0 = col0 + wn * 32 + nt * 8 + lq * 2;
            float2 v0 = make_float2(acc[mt][nt][0] * scale, acc[mt][nt][1] * scale);
            float2 v1 = make_float2(acc[mt][nt][2] * scale, acc[mt][nt][3] * scale);
            *(float2*)&C[(size_t)r0 * N + c0]       = v0;
            *(float2*)&C[(size_t)(r0 + 8) * N + c0] = v1;
        }
    }
}

// ------------------------- Tensor-core Causal Flash Attention -------------------------
#define BQ 128
#define BK 64
#define KS_ST 76
#define VS_ST 72
#define PS_ST 76

__global__ __launch_bounds__(256) void attn_mma(
    const float* __restrict__ Q, const float* __restrict__ KV,
    float* __restrict__ O)
{
    extern __shared__ float sm[];
    float* Ks = sm;                       // [64][76]
    float* Vs = Ks + BK * KS_ST;          // [64][72]
    float* Ps = Vs + BK * VS_ST;          // [128][76]

    int tid  = threadIdx.x;
    int lane = tid & 31, warp = tid >> 5;
    int lr = lane >> 2, lq = lane & 3;
    int qt = gridDim.x - 1 - blockIdx.x;
    int q0 = qt * BQ;
    int h  = blockIdx.y;
    int bb = blockIdx.z;
    int wrow = warp * 16;

    #pragma unroll
    for (int rep = 0; rep < 8; rep++) {
        int idx = tid + rep * 256;
        int r  = idx >> 4;
        int d4 = (idx & 15) * 4;
        float4 v = *(const float4*)&Q[(size_t)(bb * SEQ + q0 + r) * DM + h * DH + d4];
        *(float4*)&Ps[r * PS_ST + d4] = v;
    }
    __syncthreads();

    float qh[8][4], ql[8][4];
    #pragma unroll
    for (int ks = 0; ks < 8; ks++) {
        int base = (wrow + lr) * PS_ST + ks * 8 + lq;
        float f[4];
        f[0] = Ps[base];
        f[1] = Ps[base + 8 * PS_ST];
        f[2] = Ps[base + 4];
        f[3] = Ps[base + 8 * PS_ST + 4];
        #pragma unroll
        for (int i = 0; i < 4; i++) {
            qh[ks][i] = to_tf32(f[i]);
            ql[ks][i] = to_tf32(f[i] - qh[ks][i]);
        }
    }

    float m0 = -INFINITY, m1 = -INFINITY, l0 = 0.f, l1 = 0.f;
    float acc[8][4];
    #pragma unroll
    for (int nt = 0; nt < 8; nt++)
        #pragma unroll
        for (int i = 0; i < 4; i++) acc[nt][i] = 0.f;

    int ktiles = 2 * qt + 2;
    for (int kt = 0; kt < ktiles; kt++) {
        int t0 = kt * BK;
        __syncthreads();
        #pragma unroll
        for (int rep = 0; rep < 4; rep++) {
            int idx = tid + rep * 256;
            int c  = idx >> 4;
            int d4 = (idx & 15) * 4;
            size_t toff = (size_t)(bb * SEQ + t0 + c) * 2048 + h * DH + d4;
            *(float4*)&Ks[c * KS_ST + d4] = *(const float4*)&KV[toff];
            *(float4*)&Vs[c * VS_ST + d4] = *(const float4*)&KV[toff + 1024];
        }
        __syncthreads();

        float s[8][4];
        #pragma unroll
        for (int nt = 0; nt < 8; nt++)
            #pragma unroll
            for (int i = 0; i < 4; i++) s[nt][i] = 0.f;

        #pragma unroll
        for (int ks = 0; ks < 8; ks++) {
            #pragma unroll
            for (int nt = 0; nt < 8; nt++) {
                int ad = (nt * 8 + lr) * KS_ST + ks * 8 + lq;
                float b0 = Ks[ad], b1 = Ks[ad + 4];
                float bh[2], bl[2];
                bh[0] = to_tf32(b0); bl[0] = to_tf32(b0 - bh[0]);
                bh[1] = to_tf32(b1); bl[1] = to_tf32(b1 - bh[1]);
                mma_tf32(s[nt], qh[ks], bh);
                mma_tf32(s[nt], qh[ks], bl);
                mma_tf32(s[nt], ql[ks], bh);
            }
        }

        if (kt >= ktiles - 2) {
            int r0 = q0 + wrow + lr;
            #pragma unroll
            for (int nt = 0; nt < 8; nt++) {
                int c0 = t0 + nt * 8 + 2 * lq;
                if (c0     > r0)     s[nt][0] = -INFINITY;
                if (c0 + 1 > r0)     s[nt][1] = -INFINITY;
                if (c0     > r0 + 8) s[nt][2] = -INFINITY;
                if (c0 + 1 > r0 + 8) s[nt][3] = -INFINITY;
            }
        }

        float rx0 = -INFINITY, rx1 = -INFINITY;
        #pragma unroll
        for (int nt = 0; nt < 8; nt++) {
            rx0 = fmaxf(rx0, fmaxf(s[nt][0], s[nt][1]));
            rx1 = fmaxf(rx1, fmaxf(s[nt][2], s[nt][3]));
        }
        rx0 = fmaxf(rx0, __shfl_xor_sync(0xffffffffu, rx0, 1));
        rx0 = fmaxf(rx0, __shfl_xor_sync(0xffffffffu, rx0, 2));
        rx1 = fmaxf(rx1, __shfl_xor_sync(0xffffffffu, rx1, 1));
        rx1 = fmaxf(rx1, __shfl_xor_sync(0xffffffffu, rx1, 2));

        float mn0 = fmaxf(m0, rx0), mn1 = fmaxf(m1, rx1);
        float sc0 = __expf(m0 - mn0), sc1 = __expf(m1 - mn1);
        m0 = mn0; m1 = mn1;

        float sum0 = 0.f, sum1 = 0.f;
        #pragma unroll
        for (int nt = 0; nt < 8; nt++) {
            float p0 = __expf(s[nt][0] - mn0);
            float p1 = __expf(s[nt][1] - mn0);
            float p2 = __expf(s[nt][2] - mn1);
            float p3 = __expf(s[nt][3] - mn1);
            sum0 += p0 + p1; sum1 += p2 + p3;
            int ad = (wrow + lr) * PS_ST + nt * 8 + 2 * lq;
            *(float2*)&Ps[ad]              = make_float2(p0, p1);
            *(float2*)&Ps[ad + 8 * PS_ST]  = make_float2(p2, p3);
            acc[nt][0] *= sc0; acc[nt][1] *= sc0;
            acc[nt][2] *= sc1; acc[nt][3] *= sc1;
        }
        sum0 += __shfl_xor_sync(0xffffffffu, sum0, 1);
        sum0 += __shfl_xor_sync(0xffffffffu, sum0, 2);
        sum1 += __shfl_xor_sync(0xffffffffu, sum1, 1);
        sum1 += __shfl_xor_sync(0xffffffffu, sum1, 2);
        l0 = l0 * sc0 + sum0;
        l1 = l1 * sc1 + sum1;

        __syncwarp();

        #pragma unroll
        for (int ks = 0; ks < 8; ks++) {
            int base = (wrow + lr) * PS_ST + ks * 8 + lq;
            float f[4];
            f[0] = Ps[base];
            f[1] = Ps[base + 8 * PS_ST];
            f[2] = Ps[base + 4];
            f[3] = Ps[base + 8 * PS_ST + 4];
            float ah[4], al[4];
            #pragma unroll
            for (int i = 0; i < 4; i++) {
                ah[i] = to_tf32(f[i]);
                al[i] = to_tf32(f[i] - ah[i]);
            }
            #pragma unroll
            for (int nt = 0; nt < 8; nt++) {
                int vd = (ks * 8 + lq) * VS_ST + nt * 8 + lr;
                float b0 = Vs[vd], b1 = Vs[vd + 4 * VS_ST];
                float vh[2], vl[2];
                vh[0] = to_tf32(b0); vl[0] = to_tf32(b0 - vh[0]);
                vh[1] = to_tf32(b1); vl[1] = to_tf32(b1 - vh[1]);
                mma_tf32(acc[nt], ah, vh);
                mma_tf32(acc[nt], ah, vl);
                mma_tf32(acc[nt], al, vh);
            }
        }
    }

    float inv0 = 1.f / l0, inv1 = 1.f / l1;
    size_t row0 = (size_t)(bb * SEQ + q0 + wrow + lr);
    #pragma unroll
    for (int nt = 0; nt < 8; nt++) {
        int col = h * DH + nt * 8 + 2 * lq;
        *(float2*)&O[row0 * DM + col] =
            make_float2(acc[nt][0] * inv0, acc[nt][1] * inv0);
        *(float2*)&O[(row0 + 8) * DM + col] =
            make_float2(acc[nt][2] * inv1, acc[nt][3] * inv1);
    }
}

// ------------------------- launch -------------------------
extern "C" void kernel_launch(void* const* d_in, const int* in_sizes, int n_in,
                              void* d_out, int out_size)
{
    (void)in_sizes; (void)n_in; (void)out_size;
    const float* x       = (const float*)d_in[0];
    const float* W_dq    = (const float*)d_in[1];
    const float* W_uq    = (const float*)d_in[2];
    const float* q_ln_g  = (const float*)d_in[3];
    const float* q_ln_b  = (const float*)d_in[4];
    const float* W_dkv   = (const float*)d_in[5];
    const float* W_ukv   = (const float*)d_in[6];
    const float* kv_ln_g = (const float*)d_in[7];
    const float* kv_ln_b = (const float*)d_in[8];
    const float* preq_g  = (const float*)d_in[9];
    const float* preq_b  = (const float*)d_in[10];
    const float* prekv_g = (const float*)d_in[11];
    const float* prekv_b = (const float*)d_in[12];
    const float* wo      = (const float*)d_in[13];
    float* out = (float*)d_out;

    float *xq, *xkv, *t1, *cq, *Qp, *t2, *ckv, *KV, *ao;
    cudaGetSymbolAddress((void**)&xq,  g_xq);
    cudaGetSymbolAddress((void**)&xkv, g_xkv);
    cudaGetSymbolAddress((void**)&t1,  g_t1);
    cudaGetSymbolAddress((void**)&cq,  g_cq);
    cudaGetSymbolAddress((void**)&Qp,  g_Q);
    cudaGetSymbolAddress((void**)&t2,  g_t2);
    cudaGetSymbolAddress((void**)&ckv, g_ckv);
    cudaGetSymbolAddress((void**)&KV,  g_KV);
    cudaGetSymbolAddress((void**)&ao,  g_ao);

    int gsmemN = (2 * ASZ + 2 * 32 * BST) * (int)sizeof(float);   // TRANSB=0
    int gsmemT = (2 * ASZ + 2 * 128 * AST) * (int)sizeof(float);  // TRANSB=1
    cudaFuncSetAttribute(gemm_tf32_g<false>, cudaFuncAttributeMaxDynamicSharedMemorySize, gsmemN);
    cudaFuncSetAttribute(gemm_tf32_g<true>,  cudaFuncAttributeMaxDynamicSharedMemorySize, gsmemT);

    // pre-norms (fused pair)
    ln2_kernel<<<dim3(TOK, 2), 256>>>(x, preq_g, preq_b, xq, DM,
                                      x, prekv_g, prekv_b, xkv, DM);

    // down projections (grouped): xq@W_dq -> t1 [N=512], xkv@W_dkv -> t2 [N=1024]
    gemm_tf32_g<false><<<dim3(DM / 128, TOK / 128, 2), 256, gsmemN>>>(
        xq,  W_dq,  t1, QPJ, DM, 1.0f,
        xkv, W_dkv, t2, DM,  DM, 1.0f);

    // mid LNs (fused pair)
    ln2_kernel<<<dim3(TOK, 2), 256>>>(t1, q_ln_g, q_ln_b, cq, QPJ,
                                      t2, kv_ln_g, kv_ln_b, ckv, DM);

    // up projections (grouped): cq@W_uq -> Q [N=1024], ckv@W_ukv -> KV [N=2048]
    gemm_tf32_g<false><<<dim3(2 * DM / 128, TOK / 128, 2), 256, gsmemN>>>(
        cq,  W_uq,  Qp, DM,     QPJ, 0.125f,
        ckv, W_ukv, KV, 2 * DM, DM,  1.0f);

    // attention (tensor-core flash, split-tf32)
    int smem = (BK * KS_ST + BK * VS_ST + BQ * PS_ST) * (int)sizeof(float);
    cudaFuncSetAttribute(attn_mma, cudaFuncAttributeMaxDynamicSharedMemorySize, smem);
    attn_mma<<<dim3(SEQ / BQ, NH, 2), 256, smem>>>(Qp, KV, ao);

    // output projection: ao @ wo^T
    gemm_tf32_g<true><<<dim3(DM / 128, TOK / 128, 1), 256, gsmemT>>>(
        ao, wo, out, DM, DM, 1.0f,
        ao, wo, out, DM, DM, 1.0f);
}

// round 9
// speedup vs baseline: 2.1031x; 1.2114x over previous
#include <cuda_runtime.h>
#include <math.h>

#define TOK 4096
#define DM 1024
#define QPJ 512
#define SEQ 2048
#define NH 16
#define DH 64

// -------- scratch (static device globals: allocation-free) --------
__device__ float g_xq [TOK * DM];
__device__ float g_xkv[TOK * DM];
__device__ float g_t1 [TOK * QPJ];
__device__ float g_cq [TOK * QPJ];
__device__ float g_Q  [TOK * DM];
__device__ float g_t2 [TOK * DM];
__device__ float g_ckv[TOK * DM];
__device__ float g_KV [TOK * 2 * DM];
__device__ float g_ao [TOK * DM];

// ------------------------- helpers -------------------------
__device__ __forceinline__ float to_tf32(float x) {
    float r;
    asm("cvt.rna.tf32.f32 %0, %1;" : "=f"(r) : "f"(x));
    return r;
}

__device__ __forceinline__ void mma_tf32(float c[4], const float a[4], const float b[2]) {
    asm volatile(
        "mma.sync.aligned.m16n8k8.row.col.f32.tf32.tf32.f32 "
        "{%0,%1,%2,%3}, {%4,%5,%6,%7}, {%8,%9}, {%0,%1,%2,%3};"
        : "+f"(c[0]), "+f"(c[1]), "+f"(c[2]), "+f"(c[3])
        : "r"(__float_as_uint(a[0])), "r"(__float_as_uint(a[1])),
          "r"(__float_as_uint(a[2])), "r"(__float_as_uint(a[3])),
          "r"(__float_as_uint(b[0])), "r"(__float_as_uint(b[1])));
}

__device__ __forceinline__ void cpa16(float* dst, const float* src) {
    unsigned d = (unsigned)__cvta_generic_to_shared(dst);
    asm volatile("cp.async.cg.shared.global [%0], [%1], 16;\n" :: "r"(d), "l"(src));
}
#define CP_COMMIT() asm volatile("cp.async.commit_group;\n")
#define CP_WAIT1()  asm volatile("cp.async.wait_group 1;\n")
#define CP_WAIT0()  asm volatile("cp.async.wait_group 0;\n")

// ------------------------- fused dual LayerNorm -------------------------
__global__ __launch_bounds__(256) void ln2_kernel(
    const float* __restrict__ in0, const float* __restrict__ g0,
    const float* __restrict__ b0, float* __restrict__ o0, int D0,
    const float* __restrict__ in1, const float* __restrict__ g1,
    const float* __restrict__ b1, float* __restrict__ o1, int D1)
{
    const float* in = blockIdx.y ? in1 : in0;
    const float* gg = blockIdx.y ? g1  : g0;
    const float* bb = blockIdx.y ? b1  : b0;
    float* out      = blockIdx.y ? o1  : o0;
    int D           = blockIdx.y ? D1  : D0;

    int row = blockIdx.x;
    const float* x = in + (size_t)row * D;
    float* o = out + (size_t)row * D;
    int D4 = D >> 2;

    float s = 0.f, s2 = 0.f;
    float4 v = make_float4(0.f, 0.f, 0.f, 0.f);
    int i = threadIdx.x;
    if (i < D4) {
        v = ((const float4*)x)[i];
        s = v.x + v.y + v.z + v.w;
        s2 = v.x * v.x + v.y * v.y + v.z * v.z + v.w * v.w;
    }
    __shared__ float red[64];
    #pragma unroll
    for (int m = 16; m; m >>= 1) {
        s  += __shfl_xor_sync(0xffffffffu, s,  m);
        s2 += __shfl_xor_sync(0xffffffffu, s2, m);
    }
    int wid = threadIdx.x >> 5, lid = threadIdx.x & 31;
    if (lid == 0) { red[wid] = s; red[32 + wid] = s2; }
    __syncthreads();
    if (wid == 0) {
        s  = (lid < 8) ? red[lid]      : 0.f;
        s2 = (lid < 8) ? red[32 + lid] : 0.f;
        #pragma unroll
        for (int m = 4; m; m >>= 1) {
            s  += __shfl_xor_sync(0xffffffffu, s,  m);
            s2 += __shfl_xor_sync(0xffffffffu, s2, m);
        }
        if (lid == 0) { red[0] = s; red[1] = s2; }
    }
    __syncthreads();
    float mu  = red[0] / (float)D;
    float var = red[1] / (float)D - mu * mu;
    float r   = rsqrtf(var + 1e-5f);
    if (i < D4) {
        float4 g4 = ((const float4*)gg)[i];
        float4 b4 = ((const float4*)bb)[i];
        float4 w;
        w.x = (v.x - mu) * r * g4.x + b4.x;
        w.y = (v.y - mu) * r * g4.y + b4.y;
        w.z = (v.z - mu) * r * g4.z + b4.z;
        w.w = (v.w - mu) * r * g4.w + b4.w;
        ((float4*)o)[i] = w;
    }
}

// ------------- grouped 3-stage cp.async TF32 GEMM, 2 CTAs/SM -------------
#define AST 36
#define BST 136
#define ASZ (128 * AST)
#define NS 3

template<bool TRANSB>
__global__ __launch_bounds__(256, 2) void gemm_tf32_g(
    const float* __restrict__ A0, const float* __restrict__ B0, float* __restrict__ C0,
    int N0, int K0, float s0,
    const float* __restrict__ A1, const float* __restrict__ B1, float* __restrict__ C1,
    int N1, int K1, float s1)
{
    const float* A = blockIdx.z ? A1 : A0;
    const float* B = blockIdx.z ? B1 : B0;
    float* C       = blockIdx.z ? C1 : C0;
    int N          = blockIdx.z ? N1 : N0;
    int K          = blockIdx.z ? K1 : K0;
    float scale    = blockIdx.z ? s1 : s0;

    int col0 = blockIdx.x * 128;
    if (col0 >= N) return;
    int row0 = blockIdx.y * 128;

    extern __shared__ float gsm[];
    const int BSZ = TRANSB ? (128 * AST) : (32 * BST);
    float* Asm[NS] = { gsm, gsm + ASZ, gsm + 2 * ASZ };
    float* Bsm[NS] = { gsm + 3 * ASZ, gsm + 3 * ASZ + BSZ, gsm + 3 * ASZ + 2 * BSZ };

    int tid = threadIdx.x;
    int lane = tid & 31, warp = tid >> 5;
    int wm = warp >> 2, wn = warp & 3;
    int lr = lane >> 2, lq = lane & 3;

    float acc[4][4][4];
    #pragma unroll
    for (int a = 0; a < 4; a++)
        #pragma unroll
        for (int b = 0; b < 4; b++)
            #pragma unroll
            for (int c = 0; c < 4; c++) acc[a][b][c] = 0.f;

    int ar = tid >> 1;
    int ac = (tid & 1) * 4;
    int bk = tid >> 3;
    int bj = tid & 7;

    auto load_tile = [&](int st, int kt) {
        #pragma unroll
        for (int r = 0; r < 4; r++)
            cpa16(&Asm[st][ar * AST + (ac + r) * 4],
                  &A[(size_t)(row0 + ar) * K + kt + (ac + r) * 4]);
        if (TRANSB) {
            #pragma unroll
            for (int r = 0; r < 4; r++)
                cpa16(&Bsm[st][ar * AST + (ac + r) * 4],
                      &B[(size_t)(col0 + ar) * K + kt + (ac + r) * 4]);
        } else {
            #pragma unroll
            for (int r = 0; r < 4; r++)
                cpa16(&Bsm[st][bk * BST + (bj + r * 8) * 4],
                      &B[(size_t)(kt + bk) * N + col0 + (bj + r * 8) * 4]);
        }
    };

    int nkt = K / 32;
    load_tile(0, 0);  CP_COMMIT();
    load_tile(1, 32); CP_COMMIT();

    for (int t = 0; t < nkt; t++) {
        CP_WAIT1();
        __syncthreads();

        // fill the buffer freed by iteration t-1
        if (t + NS - 1 < nkt) load_tile((t + NS - 1) % NS, (t + NS - 1) * 32);
        CP_COMMIT();

        const float* As = Asm[t % NS];
        const float* Bs = Bsm[t % NS];
        #pragma unroll
        for (int ks = 0; ks < 4; ks++) {
            int k0 = ks * 8;
            float af[4][4], bf[4][2];
            #pragma unroll
            for (int mt = 0; mt < 4; mt++) {
                int m = wm * 64 + mt * 16 + lr;
                af[mt][0] = to_tf32(As[m * AST + k0 + lq]);
                af[mt][1] = to_tf32(As[(m + 8) * AST + k0 + lq]);
                af[mt][2] = to_tf32(As[m * AST + k0 + lq + 4]);
                af[mt][3] = to_tf32(As[(m + 8) * AST + k0 + lq + 4]);
            }
            #pragma unroll
            for (int nt = 0; nt < 4; nt++) {
                int n = wn * 32 + nt * 8 + lr;
                if (TRANSB) {
                    bf[nt][0] = to_tf32(Bs[n * AST + k0 + lq]);
                    bf[nt][1] = to_tf32(Bs[n * AST + k0 + lq + 4]);
                } else {
                    bf[nt][0] = to_tf32(Bs[(k0 + lq) * BST + n]);
                    bf[nt][1] = to_tf32(Bs[(k0 + lq + 4) * BST + n]);
                }
            }
            #pragma unroll
            for (int mt = 0; mt < 4; mt++)
                #pragma unroll
                for (int nt = 0; nt < 4; nt++)
                    mma_tf32(acc[mt][nt], af[mt], bf[nt]);
        }
    }

    #pragma unroll
    for (int mt = 0; mt < 4; mt++) {
        #pragma unroll
        for (int nt = 0; nt < 4; nt++) {
            int r0 = row0 + wm * 64 + mt * 16 + lr;
            int c0 = col0 + wn * 32 + nt * 8 + lq * 2;
            float2 v0 = make_float2(acc[mt][nt][0] * scale, acc[mt][nt][1] * scale);
            float2 v1 = make_float2(acc[mt][nt][2] * scale, acc[mt][nt][3] * scale);
            *(float2*)&C[(size_t)r0 * N + c0]       = v0;
            *(float2*)&C[(size_t)(r0 + 8) * N + c0] = v1;
        }
    }
}

// ------------------------- Tensor-core Causal Flash Attention -------------------------
// K/V pre-split into hi/lo smem once per tile (removes 8x redundant per-warp splits).
#define BQ 128
#define BK 64
#define KS_ST 76
#define VS_ST 72
#define PS_ST 76

__global__ __launch_bounds__(256) void attn_mma(
    const float* __restrict__ Q, const float* __restrict__ KV,
    float* __restrict__ O)
{
    extern __shared__ float sm[];
    float* Khi = sm;                         // [64][76]
    float* Klo = Khi + BK * KS_ST;           // [64][76]
    float* Vhi = Klo + BK * KS_ST;           // [64][72]
    float* Vlo = Vhi + BK * VS_ST;           // [64][72]
    float* Ps  = Vlo + BK * VS_ST;           // [128][76]

    int tid  = threadIdx.x;
    int lane = tid & 31, warp = tid >> 5;
    int lr = lane >> 2, lq = lane & 3;
    int qt = gridDim.x - 1 - blockIdx.x;
    int q0 = qt * BQ;
    int h  = blockIdx.y;
    int bb = blockIdx.z;
    int wrow = warp * 16;

    #pragma unroll
    for (int rep = 0; rep < 8; rep++) {
        int idx = tid + rep * 256;
        int r  = idx >> 4;
        int d4 = (idx & 15) * 4;
        float4 v = *(const float4*)&Q[(size_t)(bb * SEQ + q0 + r) * DM + h * DH + d4];
        *(float4*)&Ps[r * PS_ST + d4] = v;
    }
    __syncthreads();

    float qh[8][4], ql[8][4];
    #pragma unroll
    for (int ks = 0; ks < 8; ks++) {
        int base = (wrow + lr) * PS_ST + ks * 8 + lq;
        float f[4];
        f[0] = Ps[base];
        f[1] = Ps[base + 8 * PS_ST];
        f[2] = Ps[base + 4];
        f[3] = Ps[base + 8 * PS_ST + 4];
        #pragma unroll
        for (int i = 0; i < 4; i++) {
            qh[ks][i] = to_tf32(f[i]);
            ql[ks][i] = to_tf32(f[i] - qh[ks][i]);
        }
    }

    float m0 = -INFINITY, m1 = -INFINITY, l0 = 0.f, l1 = 0.f;
    float acc[8][4];
    #pragma unroll
    for (int nt = 0; nt < 8; nt++)
        #pragma unroll
        for (int i = 0; i < 4; i++) acc[nt][i] = 0.f;

    int ktiles = 2 * qt + 2;
    for (int kt = 0; kt < ktiles; kt++) {
        int t0 = kt * BK;
        __syncthreads();
        #pragma unroll
        for (int rep = 0; rep < 4; rep++) {
            int idx = tid + rep * 256;
            int c  = idx >> 4;
            int d4 = (idx & 15) * 4;
            size_t toff = (size_t)(bb * SEQ + t0 + c) * 2048 + h * DH + d4;
            float4 k4 = *(const float4*)&KV[toff];
            float4 v4 = *(const float4*)&KV[toff + 1024];
            float4 kh, kl, vh, vl;
            kh.x = to_tf32(k4.x); kl.x = to_tf32(k4.x - kh.x);
            kh.y = to_tf32(k4.y); kl.y = to_tf32(k4.y - kh.y);
            kh.z = to_tf32(k4.z); kl.z = to_tf32(k4.z - kh.z);
            kh.w = to_tf32(k4.w); kl.w = to_tf32(k4.w - kh.w);
            vh.x = to_tf32(v4.x); vl.x = to_tf32(v4.x - vh.x);
            vh.y = to_tf32(v4.y); vl.y = to_tf32(v4.y - vh.y);
            vh.z = to_tf32(v4.z); vl.z = to_tf32(v4.z - vh.z);
            vh.w = to_tf32(v4.w); vl.w = to_tf32(v4.w - vh.w);
            *(float4*)&Khi[c * KS_ST + d4] = kh;
            *(float4*)&Klo[c * KS_ST + d4] = kl;
            *(float4*)&Vhi[c * VS_ST + d4] = vh;
            *(float4*)&Vlo[c * VS_ST + d4] = vl;
        }
        __syncthreads();

        float s[8][4];
        #pragma unroll
        for (int nt = 0; nt < 8; nt++)
            #pragma unroll
            for (int i = 0; i < 4; i++) s[nt][i] = 0.f;

        #pragma unroll
        for (int ks = 0; ks < 8; ks++) {
            #pragma unroll
            for (int nt = 0; nt < 8; nt++) {
                int ad = (nt * 8 + lr) * KS_ST + ks * 8 + lq;
                float bh[2], bl[2];
                bh[0] = Khi[ad]; bh[1] = Khi[ad + 4];
                bl[0] = Klo[ad]; bl[1] = Klo[ad + 4];
                mma_tf32(s[nt], qh[ks], bh);
                mma_tf32(s[nt], qh[ks], bl);
                mma_tf32(s[nt], ql[ks], bh);
            }
        }

        if (kt >= ktiles - 2) {
            int r0 = q0 + wrow + lr;
            #pragma unroll
            for (int nt = 0; nt < 8; nt++) {
                int c0 = t0 + nt * 8 + 2 * lq;
                if (c0     > r0)     s[nt][0] = -INFINITY;
                if (c0 + 1 > r0)     s[nt][1] = -INFINITY;
                if (c0     > r0 + 8) s[nt][2] = -INFINITY;
                if (c0 + 1 > r0 + 8) s[nt][3] = -INFINITY;
            }
        }

        float rx0 = -INFINITY, rx1 = -INFINITY;
        #pragma unroll
        for (int nt = 0; nt < 8; nt++) {
            rx0 = fmaxf(rx0, fmaxf(s[nt][0], s[nt][1]));
            rx1 = fmaxf(rx1, fmaxf(s[nt][2], s[nt][3]));
        }
        rx0 = fmaxf(rx0, __shfl_xor_sync(0xffffffffu, rx0, 1));
        rx0 = fmaxf(rx0, __shfl_xor_sync(0xffffffffu, rx0, 2));
        rx1 = fmaxf(rx1, __shfl_xor_sync(0xffffffffu, rx1, 1));
        rx1 = fmaxf(rx1, __shfl_xor_sync(0xffffffffu, rx1, 2));

        float mn0 = fmaxf(m0, rx0), mn1 = fmaxf(m1, rx1);
        float sc0 = __expf(m0 - mn0), sc1 = __expf(m1 - mn1);
        m0 = mn0; m1 = mn1;

        float sum0 = 0.f, sum1 = 0.f;
        #pragma unroll
        for (int nt = 0; nt < 8; nt++) {
            float p0 = __expf(s[nt][0] - mn0);
            float p1 = __expf(s[nt][1] - mn0);
            float p2 = __expf(s[nt][2] - mn1);
            float p3 = __expf(s[nt][3] - mn1);
            sum0 += p0 + p1; sum1 += p2 + p3;
            int ad = (wrow + lr) * PS_ST + nt * 8 + 2 * lq;
            *(float2*)&Ps[ad]              = make_float2(p0, p1);
            *(float2*)&Ps[ad + 8 * PS_ST]  = make_float2(p2, p3);
            acc[nt][0] *= sc0; acc[nt][1] *= sc0;
            acc[nt][2] *= sc1; acc[nt][3] *= sc1;
        }
        sum0 += __shfl_xor_sync(0xffffffffu, sum0, 1);
        sum0 += __shfl_xor_sync(0xffffffffu, sum0, 2);
        sum1 += __shfl_xor_sync(0xffffffffu, sum1, 1);
        sum1 += __shfl_xor_sync(0xffffffffu, sum1, 2);
        l0 = l0 * sc0 + sum0;
        l1 = l1 * sc1 + sum1;

        __syncwarp();

        #pragma unroll
        for (int ks = 0; ks < 8; ks++) {
            int base = (wrow + lr) * PS_ST + ks * 8 + lq;
            float f[4];
            f[0] = Ps[base];
            f[1] = Ps[base + 8 * PS_ST];
            f[2] = Ps[base + 4];
            f[3] = Ps[base + 8 * PS_ST + 4];
            float ah[4], al[4];
            #pragma unroll
            for (int i = 0; i < 4; i++) {
                ah[i] = to_tf32(f[i]);
                al[i] = to_tf32(f[i] - ah[i]);
            }
            #pragma unroll
            for (int nt = 0; nt < 8; nt++) {
                int vd = (ks * 8 + lq) * VS_ST + nt * 8 + lr;
                float vh[2], vl[2];
                vh[0] = Vhi[vd]; vh[1] = Vhi[vd + 4 * VS_ST];
                vl[0] = Vlo[vd]; vl[1] = Vlo[vd + 4 * VS_ST];
                mma_tf32(acc[nt], ah, vh);
                mma_tf32(acc[nt], ah, vl);
                mma_tf32(acc[nt], al, vh);
            }
        }
    }

    float inv0 = 1.f / l0, inv1 = 1.f / l1;
    size_t row0 = (size_t)(bb * SEQ + q0 + wrow + lr);
    #pragma unroll
    for (int nt = 0; nt < 8; nt++) {
        int col = h * DH + nt * 8 + 2 * lq;
        *(float2*)&O[row0 * DM + col] =
            make_float2(acc[nt][0] * inv0, acc[nt][1] * inv0);
        *(float2*)&O[(row0 + 8) * DM + col] =
            make_float2(acc[nt][2] * inv1, acc[nt][3] * inv1);
    }
}

// ------------------------- launch -------------------------
extern "C" void kernel_launch(void* const* d_in, const int* in_sizes, int n_in,
                              void* d_out, int out_size)
{
    (void)in_sizes; (void)n_in; (void)out_size;
    const float* x       = (const float*)d_in[0];
    const float* W_dq    = (const float*)d_in[1];
    const float* W_uq    = (const float*)d_in[2];
    const float* q_ln_g  = (const float*)d_in[3];
    const float* q_ln_b  = (const float*)d_in[4];
    const float* W_dkv   = (const float*)d_in[5];
    const float* W_ukv   = (const float*)d_in[6];
    const float* kv_ln_g = (const float*)d_in[7];
    const float* kv_ln_b = (const float*)d_in[8];
    const float* preq_g  = (const float*)d_in[9];
    const float* preq_b  = (const float*)d_in[10];
    const float* prekv_g = (const float*)d_in[11];
    const float* prekv_b = (const float*)d_in[12];
    const float* wo      = (const float*)d_in[13];
    float* out = (float*)d_out;

    float *xq, *xkv, *t1, *cq, *Qp, *t2, *ckv, *KV, *ao;
    cudaGetSymbolAddress((void**)&xq,  g_xq);
    cudaGetSymbolAddress((void**)&xkv, g_xkv);
    cudaGetSymbolAddress((void**)&t1,  g_t1);
    cudaGetSymbolAddress((void**)&cq,  g_cq);
    cudaGetSymbolAddress((void**)&Qp,  g_Q);
    cudaGetSymbolAddress((void**)&t2,  g_t2);
    cudaGetSymbolAddress((void**)&ckv, g_ckv);
    cudaGetSymbolAddress((void**)&KV,  g_KV);
    cudaGetSymbolAddress((void**)&ao,  g_ao);

    int gsmemN = NS * (ASZ + 32 * BST) * (int)sizeof(float);   // TRANSB=0: 107.5 KB
    int gsmemT = NS * (ASZ + 128 * AST) * (int)sizeof(float);  // TRANSB=1: 110.6 KB
    cudaFuncSetAttribute(gemm_tf32_g<false>, cudaFuncAttributeMaxDynamicSharedMemorySize, gsmemN);
    cudaFuncSetAttribute(gemm_tf32_g<true>,  cudaFuncAttributeMaxDynamicSharedMemorySize, gsmemT);

    // pre-norms (fused pair)
    ln2_kernel<<<dim3(TOK, 2), 256>>>(x, preq_g, preq_b, xq, DM,
                                      x, prekv_g, prekv_b, xkv, DM);

    // down projections (grouped)
    gemm_tf32_g<false><<<dim3(DM / 128, TOK / 128, 2), 256, gsmemN>>>(
        xq,  W_dq,  t1, QPJ, DM, 1.0f,
        xkv, W_dkv, t2, DM,  DM, 1.0f);

    // mid LNs (fused pair)
    ln2_kernel<<<dim3(TOK, 2), 256>>>(t1, q_ln_g, q_ln_b, cq, QPJ,
                                      t2, kv_ln_g, kv_ln_b, ckv, DM);

    // up projections (grouped)
    gemm_tf32_g<false><<<dim3(2 * DM / 128, TOK / 128, 2), 256, gsmemN>>>(
        cq,  W_uq,  Qp, DM,     QPJ, 0.125f,
        ckv, W_ukv, KV, 2 * DM, DM,  1.0f);

    // attention (tensor-core flash, split-tf32, pre-split K/V)
    int smem = (2 * BK * KS_ST + 2 * BK * VS_ST + BQ * PS_ST) * (int)sizeof(float);
    cudaFuncSetAttribute(attn_mma, cudaFuncAttributeMaxDynamicSharedMemorySize, smem);
    attn_mma<<<dim3(SEQ / BQ, NH, 2), 256, smem>>>(Qp, KV, ao);

    // output projection: ao @ wo^T
    gemm_tf32_g<true><<<dim3(DM / 128, TOK / 128, 1), 256, gsmemT>>>(
        ao, wo, out, DM, DM, 1.0f,
        ao, wo, out, DM, DM, 1.0f);
}